// round 8
// baseline (speedup 1.0000x reference)
#include <cuda_runtime.h>
#include <cstdint>

// ---------------------------------------------------------------------------
// QuantumDMRGLayer on GB300 (sm_103a)  —  v4: 64-row tiles, 2 CTAs/SM
//
// left  chain: 97 steps, carry_new(128) = [xi0*c | xi1*c](256) @ Wl[s](256x128)
// right chain: 96 steps (reverse order), inner 128x128 blocks transposed
// final      : out[b,l] = sum_n right[b,n] * ( A_lab[b,:] @ WL_l )[b,n]
//
// All GEMMs: mma.sync.m16n8k8 tf32, fp32 accumulate. Every tf32 operand is
// RN-rounded exactly once (weights in prep kernels, carries in epilogues).
//
// v4 vs v3b: scan uses 256 CTAs x 256 threads (64 batch rows each), 8 warps
// in a 2(m) x 4(n) grid, W double-buffered. 2 CTAs co-resident per SM so
// one CTA's barrier/cp.async stalls are filled by the other's MMA issue.
// ---------------------------------------------------------------------------

#define BATCH    8192
#define DIMVEC   196
#define XROW     (DIMVEC * 2)
#define MDIM     128
#define NLSTEPS  97
#define NRSTEPS  96
#define WSTEP    (256 * MDIM)      // 32768 floats per step weight matrix
#define SLICEF   (32 * MDIM)       // 4096 floats per 32-k slice

#define APITCH   260               // A smem pitch: conflict-free fragment loads
#define WPITCH   136               // W smem pitch: conflict-free fragment loads
#define RPITCH   132

static const int SMEM_SCAN  = (64 * APITCH + 2 * 32 * WPITCH) * 4;                        // 101,376
static const int SMEM_FINAL = (64 * APITCH + 2 * 32 * WPITCH + 64 * RPITCH + 64 * 4) * 4; // 136,192

// -------------------- device scratch (static: allocation-free) -------------
__device__ __align__(128) float g_wl  [NLSTEPS * WSTEP];
__device__ __align__(128) float g_wr  [NRSTEPS * WSTEP];   // step-reversed + transposed
__device__ __align__(128) float g_wlab[10 * WSTEP];
__device__ __align__(128) float g_left [BATCH * MDIM];
__device__ __align__(128) float g_right[BATCH * MDIM];

// -------------------- helpers ----------------------------------------------
__device__ __forceinline__ float tf32r(float v) {
    uint32_t u;
    asm("cvt.rna.tf32.f32 %0, %1;" : "=r"(u) : "f"(v));
    return __uint_as_float(u);
}

__device__ __forceinline__ void mma_tf32(float d[4], const uint32_t a[4],
                                         uint32_t b0, uint32_t b1) {
    asm volatile(
        "mma.sync.aligned.m16n8k8.row.col.f32.tf32.tf32.f32 "
        "{%0,%1,%2,%3}, {%4,%5,%6,%7}, {%8,%9}, {%0,%1,%2,%3};\n"
        : "+f"(d[0]), "+f"(d[1]), "+f"(d[2]), "+f"(d[3])
        : "r"(a[0]), "r"(a[1]), "r"(a[2]), "r"(a[3]), "r"(b0), "r"(b1));
}

// Stage one 32(k) x 128(n) fp32 W slice (16 KB = 1024 x 16B chunks) into
// padded smem. Each of NT threads copies 1024/NT chunks.
template <int NT>
__device__ __forceinline__ void stage32(float* dst, const float* __restrict__ src, int tid) {
#pragma unroll
    for (int i = 0; i < 1024 / NT; i++) {
        int chunk = tid + i * NT;
        int row   = chunk >> 5;             // 0..31
        int c     = (chunk & 31) * 4;       // 0..124
        uint32_t s = (uint32_t)__cvta_generic_to_shared(dst + row * WPITCH + c);
        asm volatile("cp.async.cg.shared.global [%0], [%1], 16;"
                     :: "r"(s), "l"(src + row * MDIM + c));
    }
    asm volatile("cp.async.commit_group;" ::: "memory");
}

// ======================= prep kernels ======================================
__global__ void prep_left_k(const float* __restrict__ src) {
    int i = (blockIdx.x * 256 + threadIdx.x) * 4;
    float4 v = *reinterpret_cast<const float4*>(src + i);
    v.x = tf32r(v.x); v.y = tf32r(v.y); v.z = tf32r(v.z); v.w = tf32r(v.w);
    *reinterpret_cast<float4*>(g_wl + i) = v;
}

// dst[((j*2+s2)*128+m)*128+n] = rn( src[(((95-j)*2+s2)*128+n)*128+m] )
__global__ void prep_right_k(const float* __restrict__ src) {
    int gid = blockIdx.x * 256 + threadIdx.x;
    int didx = gid * 4;
    int n  = didx & 127;
    int m  = (didx >> 7) & 127;
    int s2 = (didx >> 14) & 1;
    int j  = didx >> 15;
    int s  = 95 - j;
    const float* sb = src + (((size_t)(s * 2 + s2)) * 128) * 128 + m;
    float4 v;
    v.x = tf32r(__ldg(sb + (size_t)(n + 0) * 128));
    v.y = tf32r(__ldg(sb + (size_t)(n + 1) * 128));
    v.z = tf32r(__ldg(sb + (size_t)(n + 2) * 128));
    v.w = tf32r(__ldg(sb + (size_t)(n + 3) * 128));
    *reinterpret_cast<float4*>(g_wr + didx) = v;
}

// dst[l*WSTEP + (p*128+m)*128 + n] = rn( src[((p*128+m)*128+n)*10 + l] )
__global__ void prep_label_k(const float* __restrict__ src) {
    int gid = blockIdx.x * 256 + threadIdx.x;
    int n = gid & 127;
    int m = (gid >> 7) & 127;
    int p = (gid >> 14) & 1;
    int l = gid >> 15;
    int sidx = ((p << 14) | (m << 7) | n) * 10 + l;
    g_wlab[gid] = tf32r(__ldg(src + sidx));
}

// ======================= scan kernel =======================================
// 256 CTAs x 256 threads, 2 CTAs/SM. C-tile 64(m) x 128(n), K=256. 8 warps
// in a 2(m) x 4(n) grid; per-warp 32x32 tile, acc[2][4][4].
__device__ __forceinline__ void compute_slice(const float* __restrict__ As,
                                              const float* __restrict__ Wb,
                                              int kb, float acc[2][4][4],
                                              int wm, int wn, int g, int t) {
    const uint32_t* Au = reinterpret_cast<const uint32_t*>(As);
    const uint32_t* Wu = reinterpret_cast<const uint32_t*>(Wb);
#pragma unroll
    for (int kk = 0; kk < 32; kk += 8) {
        uint32_t a[2][4];
#pragma unroll
        for (int i = 0; i < 2; i++) {
            int r = wm * 32 + i * 16 + g;
            int k = kb + kk + t;
            a[i][0] = Au[r * APITCH + k];
            a[i][1] = Au[(r + 8) * APITCH + k];
            a[i][2] = Au[r * APITCH + k + 4];
            a[i][3] = Au[(r + 8) * APITCH + k + 4];
        }
#pragma unroll
        for (int jj = 0; jj < 4; jj++) {
            int cn = wn * 32 + jj * 8 + g;
            uint32_t b0 = Wu[(kk + t) * WPITCH + cn];
            uint32_t b1 = Wu[(kk + t + 4) * WPITCH + cn];
            mma_tf32(acc[0][jj], a[0], b0, b1);
            mma_tf32(acc[1][jj], a[1], b0, b1);
        }
    }
}

__global__ __launch_bounds__(256, 2)
void scan_kernel(const float* __restrict__ x,
                 const float* __restrict__ w0,
                 const float* __restrict__ wend) {
    extern __shared__ float smem[];
    float* As = smem;                              // 64 x APITCH
    float* Wb[2] = { smem + 64 * APITCH,
                     smem + 64 * APITCH + 32 * WPITCH };

    const bool is_left = blockIdx.x < 128;
    const int  b0 = (blockIdx.x & 127) * 64;
    const int  S  = is_left ? NLSTEPS : NRSTEPS;
    const int  NS = S * 8;                         // total 32-k slices
    const float* Wg = is_left ? g_wl : g_wr;
    const float* iw = is_left ? w0 : wend;
    const int tid = threadIdx.x;

    // ---- init: carry = x[iv] @ iw (fp32 FMA), build A for step 0 ----
    {
        int r = tid & 63, q = tid >> 6;            // q in 0..3
        const float* xr = x + (size_t)(b0 + r) * XROW;
        int iv = is_left ? 0 : 195;
        int xi = is_left ? 1 : 194;
        float x0 = xr[iv * 2], x1 = xr[iv * 2 + 1];
        float xi0 = xr[xi * 2], xi1 = xr[xi * 2 + 1];
        for (int m = q * 32; m < q * 32 + 32; m++) {
            float v = x0 * iw[m] + x1 * iw[MDIM + m];
            As[r * APITCH + m]       = tf32r(xi0 * v);
            As[r * APITCH + 128 + m] = tf32r(xi1 * v);
        }
    }

    // prologue: stage slice 0
    stage32<256>(Wb[0], Wg, tid);
    __syncthreads();   // A visible to all warps

    const int warp = tid >> 5, lane = tid & 31, g = lane >> 2, t = lane & 3;
    const int wm = warp >> 2, wn = warp & 3;       // wm 0..1, wn 0..3

    for (int j = 0; j < S; j++) {
        float acc[2][4][4];
#pragma unroll
        for (int i = 0; i < 2; i++)
#pragma unroll
            for (int jj = 0; jj < 4; jj++)
#pragma unroll
                for (int q = 0; q < 4; q++) acc[i][jj][q] = 0.f;

#pragma unroll 1
        for (int ks = 0; ks < 8; ks++) {
            int gs = j * 8 + ks;
            asm volatile("cp.async.wait_group 0;" ::: "memory");  // slice gs landed
            __syncthreads();   // staged data visible; all warps past compute(gs-1)
            if (gs + 1 < NS)   // stage next into buffer that held slice gs-1
                stage32<256>(Wb[(gs + 1) & 1], Wg + (size_t)(gs + 1) * SLICEF, tid);
            compute_slice(As, Wb[gs & 1], ks * 32, acc, wm, wn, g, t);
        }
        __syncthreads();       // all compute done before A overwrite

        if (j + 1 < S) {
            // epilogue: A <- tf32( xi(j+1) * carry_new )
            int xin = is_left ? (2 + j) : (193 - j);
#pragma unroll
            for (int i = 0; i < 2; i++) {
                int r0 = wm * 32 + i * 16 + g;
                const float* xr0 = x + (size_t)(b0 + r0) * XROW + xin * 2;
                const float* xr1 = x + (size_t)(b0 + r0 + 8) * XROW + xin * 2;
                float p00 = __ldg(xr0), p01 = __ldg(xr0 + 1);
                float p10 = __ldg(xr1), p11 = __ldg(xr1 + 1);
#pragma unroll
                for (int jj = 0; jj < 4; jj++) {
                    int c0 = wn * 32 + jj * 8 + 2 * t;
                    float d0 = acc[i][jj][0], d1 = acc[i][jj][1];
                    float d2 = acc[i][jj][2], d3 = acc[i][jj][3];
                    *(float2*)&As[r0 * APITCH + c0]             = make_float2(tf32r(p00 * d0), tf32r(p00 * d1));
                    *(float2*)&As[r0 * APITCH + 128 + c0]       = make_float2(tf32r(p01 * d0), tf32r(p01 * d1));
                    *(float2*)&As[(r0 + 8) * APITCH + c0]       = make_float2(tf32r(p10 * d2), tf32r(p10 * d3));
                    *(float2*)&As[(r0 + 8) * APITCH + 128 + c0] = make_float2(tf32r(p11 * d2), tf32r(p11 * d3));
                }
            }
            // visibility before next step's compute: sync inside next slice iter
        } else {
            float* dst = is_left ? g_left : g_right;
#pragma unroll
            for (int i = 0; i < 2; i++) {
                int r0 = wm * 32 + i * 16 + g;
#pragma unroll
                for (int jj = 0; jj < 4; jj++) {
                    int c0 = wn * 32 + jj * 8 + 2 * t;
                    *(float2*)&dst[(size_t)(b0 + r0) * MDIM + c0]     = make_float2(acc[i][jj][0], acc[i][jj][1]);
                    *(float2*)&dst[(size_t)(b0 + r0 + 8) * MDIM + c0] = make_float2(acc[i][jj][2], acc[i][jj][3]);
                }
            }
        }
    }
}

// ======================= final kernel ======================================
// 128 CTAs x 64 batch rows, 256 threads. C-tile 64x128: 8 warps, wm 0..1,
// wn 0..3. 10 label GEMMs + deterministic smem-tree reduction (no atomics).
__global__ __launch_bounds__(256, 1)
void final_kernel(const float* __restrict__ x, float* __restrict__ out) {
    extern __shared__ float smem[];
    float* As  = smem;                       // 64 x APITCH
    float* Wb0 = As + 64 * APITCH;
    float* Wb1 = Wb0 + 32 * WPITCH;
    float* sR  = Wb1 + 32 * WPITCH;          // 64 x RPITCH
    float* sP  = sR + 64 * RPITCH;           // 64 x 4 partials

    const int b0 = blockIdx.x * 64;
    const int tid = threadIdx.x;

    {
        int r = tid >> 2, q = tid & 3;
        const float* xr = x + (size_t)(b0 + r) * XROW + 98 * 2;
        float xl0 = __ldg(xr), xl1 = __ldg(xr + 1);
        for (int m = q * 32; m < q * 32 + 32; m++) {
            float v = g_left[(size_t)(b0 + r) * MDIM + m];
            As[r * APITCH + m]       = tf32r(xl0 * v);
            As[r * APITCH + 128 + m] = tf32r(xl1 * v);
            sR[r * RPITCH + m] = g_right[(size_t)(b0 + r) * MDIM + m];
        }
    }
    __syncthreads();

    const int warp = tid >> 5, lane = tid & 31, g = lane >> 2, t = lane & 3;
    const int wm = warp >> 2, wn = warp & 3;

    for (int l = 0; l < 10; l++) {
        const float* W = g_wlab + (size_t)l * WSTEP;
        float acc[2][4][4];
#pragma unroll
        for (int i = 0; i < 2; i++)
#pragma unroll
            for (int jj = 0; jj < 4; jj++)
#pragma unroll
                for (int q = 0; q < 4; q++) acc[i][jj][q] = 0.f;

        stage32<256>(Wb0, W, tid);
#pragma unroll 1
        for (int ks = 0; ks < 8; ks++) {
            float* cur = (ks & 1) ? Wb1 : Wb0;
            if (ks < 7) {
                float* nxt = (ks & 1) ? Wb0 : Wb1;
                stage32<256>(nxt, W + (ks + 1) * SLICEF, tid);
                asm volatile("cp.async.wait_group 1;" ::: "memory");
            } else {
                asm volatile("cp.async.wait_group 0;" ::: "memory");
            }
            __syncthreads();
            compute_slice(As, cur, ks * 32, acc, wm, wn, g, t);
            __syncthreads();
        }

#pragma unroll
        for (int i = 0; i < 2; i++) {
            int r0 = wm * 32 + i * 16 + g;
            float p0 = 0.f, p1 = 0.f;
#pragma unroll
            for (int jj = 0; jj < 4; jj++) {
                int c0 = wn * 32 + jj * 8 + 2 * t;
                p0 += acc[i][jj][0] * sR[r0 * RPITCH + c0]
                    + acc[i][jj][1] * sR[r0 * RPITCH + c0 + 1];
                p1 += acc[i][jj][2] * sR[(r0 + 8) * RPITCH + c0]
                    + acc[i][jj][3] * sR[(r0 + 8) * RPITCH + c0 + 1];
            }
            p0 += __shfl_xor_sync(0xffffffffu, p0, 1);
            p0 += __shfl_xor_sync(0xffffffffu, p0, 2);
            p1 += __shfl_xor_sync(0xffffffffu, p1, 1);
            p1 += __shfl_xor_sync(0xffffffffu, p1, 2);
            if (t == 0) {
                sP[r0 * 4 + wn]       = p0;
                sP[(r0 + 8) * 4 + wn] = p1;
            }
        }
        __syncthreads();
        if (tid < 64) {
            float s = sP[tid * 4] + sP[tid * 4 + 1] + sP[tid * 4 + 2] + sP[tid * 4 + 3];
            out[(size_t)(b0 + tid) * 10 + l] = s;
        }
        __syncthreads();
    }
}

// ======================= launch ============================================
extern "C" void kernel_launch(void* const* d_in, const int* in_sizes, int n_in,
                              void* d_out, int out_size) {
    const float *x = nullptr, *w0 = nullptr, *wl = nullptr,
                *wlab = nullptr, *wr = nullptr, *wend = nullptr;
    for (int i = 0; i < n_in; i++) {
        const float* p = (const float*)d_in[i];
        switch (in_sizes[i]) {
            case 3211264: x = p; break;
            case 3178496: wl = p; break;
            case 327680:  wlab = p; break;
            case 3145728: wr = p; break;
            case 256:     if (!w0) w0 = p; else wend = p; break;
            default: break;
        }
    }
    if (!x || !w0 || !wl || !wlab || !wr || !wend) return;

    cudaFuncSetAttribute(scan_kernel,  cudaFuncAttributeMaxDynamicSharedMemorySize, SMEM_SCAN);
    cudaFuncSetAttribute(final_kernel, cudaFuncAttributeMaxDynamicSharedMemorySize, SMEM_FINAL);

    prep_left_k <<<3104, 256>>>(wl);
    prep_right_k<<<3072, 256>>>(wr);
    prep_label_k<<<1280, 256>>>(wlab);
    scan_kernel <<<256, 256, SMEM_SCAN>>>(x, w0, wend);
    final_kernel<<<128, 256, SMEM_FINAL>>>(x, (float*)d_out);
}

// round 9
// speedup vs baseline: 1.0019x; 1.0019x over previous
#include <cuda_runtime.h>
#include <cstdint>

// ---------------------------------------------------------------------------
// QuantumDMRGLayer on GB300 (sm_103a)  —  v5: quarter-step W ring, long phases
//
// left  chain: 97 steps, carry_new(128) = [xi0*c | xi1*c](256) @ Wl[s](256x128)
// right chain: 96 steps (reverse order), inner 128x128 blocks transposed
// final      : out[b,l] = sum_n right[b,n] * ( A_lab[b,:] @ WL_l )[b,n]
//
// All GEMMs: mma.sync.m16n8k8 tf32, fp32 accumulate. Every tf32 operand is
// RN-rounded exactly once (weights in prep kernels, carries in epilogues).
//
// v5 scan: 128 CTAs x 256 thr (1/SM), C-tile 128x128, 8 warps in 2(m) x 4(n)
// grid (64x32 warp tiles). W streamed in 64-k-row quarters (32 KB), 2-deep
// ring -> 5 syncthreads per step instead of 17; long LDS/MMA phases let the
// two warps per SMSP desynchronize and overlap memory against tensor.
// ---------------------------------------------------------------------------

#define BATCH    8192
#define DIMVEC   196
#define XROW     (DIMVEC * 2)
#define MDIM     128
#define NLSTEPS  97
#define NRSTEPS  96
#define WSTEP    (256 * MDIM)      // 32768 floats per step weight matrix
#define QROWS    64                // k-rows per staged quarter
#define QF       (QROWS * MDIM)    // 8192 floats per quarter

#define APITCH   260               // A pitch (mod 32 = 4): conflict-free frags
#define WPITCH   132               // W pitch (mod 32 = 4): conflict-free frags
#define RPITCH   132

static const int SMEM_SCAN  = (128 * APITCH + 2 * QROWS * WPITCH) * 4;                    // 200,704
static const int SMEM_FINAL = (64 * APITCH + 2 * 32 * 136 + 64 * RPITCH + 64 * 4) * 4;    // 136,192
#define WPITCH_F 136               // final kernel keeps v3b 32-row slices

// -------------------- device scratch (static: allocation-free) -------------
__device__ __align__(128) float g_wl  [NLSTEPS * WSTEP];
__device__ __align__(128) float g_wr  [NRSTEPS * WSTEP];   // step-reversed + transposed
__device__ __align__(128) float g_wlab[10 * WSTEP];
__device__ __align__(128) float g_left [BATCH * MDIM];
__device__ __align__(128) float g_right[BATCH * MDIM];

// -------------------- helpers ----------------------------------------------
__device__ __forceinline__ float tf32r(float v) {
    uint32_t u;
    asm("cvt.rna.tf32.f32 %0, %1;" : "=r"(u) : "f"(v));
    return __uint_as_float(u);
}

__device__ __forceinline__ void mma_tf32(float d[4], const uint32_t a[4],
                                         uint32_t b0, uint32_t b1) {
    asm volatile(
        "mma.sync.aligned.m16n8k8.row.col.f32.tf32.tf32.f32 "
        "{%0,%1,%2,%3}, {%4,%5,%6,%7}, {%8,%9}, {%0,%1,%2,%3};\n"
        : "+f"(d[0]), "+f"(d[1]), "+f"(d[2]), "+f"(d[3])
        : "r"(a[0]), "r"(a[1]), "r"(a[2]), "r"(a[3]), "r"(b0), "r"(b1));
}

// Stage one 64(k) x 128(n) fp32 W quarter (32 KB = 2048 x 16B chunks).
__device__ __forceinline__ void stageQ(float* dst, const float* __restrict__ src, int tid) {
#pragma unroll
    for (int i = 0; i < 8; i++) {
        int chunk = tid + i * 256;          // 0..2047
        int row   = chunk >> 5;             // 0..63
        int c     = (chunk & 31) * 4;       // 0..124
        uint32_t s = (uint32_t)__cvta_generic_to_shared(dst + row * WPITCH + c);
        asm volatile("cp.async.cg.shared.global [%0], [%1], 16;"
                     :: "r"(s), "l"(src + row * MDIM + c));
    }
    asm volatile("cp.async.commit_group;" ::: "memory");
}

// Stage one 32(k) x 128(n) slice with pitch 136 (final kernel, v3b layout).
__device__ __forceinline__ void stage32f(float* dst, const float* __restrict__ src, int tid) {
#pragma unroll
    for (int i = 0; i < 4; i++) {
        int chunk = tid + i * 256;
        int row   = chunk >> 5;
        int c     = (chunk & 31) * 4;
        uint32_t s = (uint32_t)__cvta_generic_to_shared(dst + row * WPITCH_F + c);
        asm volatile("cp.async.cg.shared.global [%0], [%1], 16;"
                     :: "r"(s), "l"(src + row * MDIM + c));
    }
    asm volatile("cp.async.commit_group;" ::: "memory");
}

// ======================= prep kernels ======================================
__global__ void prep_left_k(const float* __restrict__ src) {
    int i = (blockIdx.x * 256 + threadIdx.x) * 4;
    float4 v = *reinterpret_cast<const float4*>(src + i);
    v.x = tf32r(v.x); v.y = tf32r(v.y); v.z = tf32r(v.z); v.w = tf32r(v.w);
    *reinterpret_cast<float4*>(g_wl + i) = v;
}

// dst[((j*2+s2)*128+m)*128+n] = rn( src[(((95-j)*2+s2)*128+n)*128+m] )
__global__ void prep_right_k(const float* __restrict__ src) {
    int gid = blockIdx.x * 256 + threadIdx.x;
    int didx = gid * 4;
    int n  = didx & 127;
    int m  = (didx >> 7) & 127;
    int s2 = (didx >> 14) & 1;
    int j  = didx >> 15;
    int s  = 95 - j;
    const float* sb = src + (((size_t)(s * 2 + s2)) * 128) * 128 + m;
    float4 v;
    v.x = tf32r(__ldg(sb + (size_t)(n + 0) * 128));
    v.y = tf32r(__ldg(sb + (size_t)(n + 1) * 128));
    v.z = tf32r(__ldg(sb + (size_t)(n + 2) * 128));
    v.w = tf32r(__ldg(sb + (size_t)(n + 3) * 128));
    *reinterpret_cast<float4*>(g_wr + didx) = v;
}

// dst[l*WSTEP + (p*128+m)*128 + n] = rn( src[((p*128+m)*128+n)*10 + l] )
__global__ void prep_label_k(const float* __restrict__ src) {
    int gid = blockIdx.x * 256 + threadIdx.x;
    int n = gid & 127;
    int m = (gid >> 7) & 127;
    int p = (gid >> 14) & 1;
    int l = gid >> 15;
    int sidx = ((p << 14) | (m << 7) | n) * 10 + l;
    g_wlab[gid] = tf32r(__ldg(src + sidx));
}

// ======================= scan kernel =======================================
// Warp tile 64(m) x 32(n): i in 0..3 (16-row subtiles), jj in 0..3 (8-col).
// acc[4][4][4] = 64 regs. Per 8-k chunk: 16 A-loads + 8 B-loads + 16 MMAs.
__device__ __forceinline__ void compute_quarter(const float* __restrict__ As,
                                                const float* __restrict__ Wb,
                                                int akb, float acc[4][4][4],
                                                int wm, int wn, int g, int t) {
    const uint32_t* Au = reinterpret_cast<const uint32_t*>(As);
    const uint32_t* Wu = reinterpret_cast<const uint32_t*>(Wb);
#pragma unroll
    for (int kk = 0; kk < QROWS; kk += 8) {
        uint32_t a[4][4];
#pragma unroll
        for (int i = 0; i < 4; i++) {
            int r = wm * 64 + i * 16 + g;
            int k = akb + kk + t;
            a[i][0] = Au[r * APITCH + k];
            a[i][1] = Au[(r + 8) * APITCH + k];
            a[i][2] = Au[r * APITCH + k + 4];
            a[i][3] = Au[(r + 8) * APITCH + k + 4];
        }
#pragma unroll
        for (int jj = 0; jj < 4; jj++) {
            int cn = wn * 32 + jj * 8 + g;
            uint32_t b0 = Wu[(kk + t) * WPITCH + cn];
            uint32_t b1 = Wu[(kk + t + 4) * WPITCH + cn];
#pragma unroll
            for (int i = 0; i < 4; i++)
                mma_tf32(acc[i][jj], a[i], b0, b1);
        }
    }
}

__global__ __launch_bounds__(256, 1)
void scan_kernel(const float* __restrict__ x,
                 const float* __restrict__ w0,
                 const float* __restrict__ wend) {
    extern __shared__ float smem[];
    float* As = smem;                              // 128 x APITCH
    float* Wb[2] = { smem + 128 * APITCH,
                     smem + 128 * APITCH + QROWS * WPITCH };

    const bool is_left = blockIdx.x < 64;
    const int  b0 = (blockIdx.x & 63) * 128;
    const int  S  = is_left ? NLSTEPS : NRSTEPS;
    const int  NQ = S * 4;                         // total 64-k quarters
    const float* Wg = is_left ? g_wl : g_wr;
    const float* iw = is_left ? w0 : wend;
    const int tid = threadIdx.x;

    // ---- init: carry = x[iv] @ iw (fp32 FMA), build A for step 0 ----
    {
        int r = tid & 127, q = tid >> 7;           // q in 0..1
        const float* xr = x + (size_t)(b0 + r) * XROW;
        int iv = is_left ? 0 : 195;
        int xi = is_left ? 1 : 194;
        float x0 = xr[iv * 2], x1 = xr[iv * 2 + 1];
        float xi0 = xr[xi * 2], xi1 = xr[xi * 2 + 1];
        for (int m = q * 64; m < q * 64 + 64; m++) {
            float v = x0 * iw[m] + x1 * iw[MDIM + m];
            As[r * APITCH + m]       = tf32r(xi0 * v);
            As[r * APITCH + 128 + m] = tf32r(xi1 * v);
        }
    }

    // prologue: stage quarter 0
    stageQ(Wb[0], Wg, tid);

    const int warp = tid >> 5, lane = tid & 31, g = lane >> 2, t = lane & 3;
    const int wm = warp >> 2, wn = warp & 3;       // wm 0..1, wn 0..3

    for (int j = 0; j < S; j++) {
        float acc[4][4][4];
#pragma unroll
        for (int i = 0; i < 4; i++)
#pragma unroll
            for (int jj = 0; jj < 4; jj++)
#pragma unroll
                for (int q = 0; q < 4; q++) acc[i][jj][q] = 0.f;

#pragma unroll 1
        for (int qs = 0; qs < 4; qs++) {
            int gq = j * 4 + qs;
            asm volatile("cp.async.wait_group 0;" ::: "memory");  // quarter gq landed
            __syncthreads();   // staged data + (qs==0) rebuilt A visible;
                               // all warps past compute(gq-1) -> its buffer free
            if (gq + 1 < NQ)
                stageQ(Wb[(gq + 1) & 1], Wg + (size_t)(gq + 1) * QF, tid);
            compute_quarter(As, Wb[gq & 1], qs * QROWS, acc, wm, wn, g, t);
        }
        __syncthreads();       // all compute done before A overwrite

        if (j + 1 < S) {
            // epilogue: A <- tf32( xi(j+1) * carry_new )
            int xin = is_left ? (2 + j) : (193 - j);
#pragma unroll
            for (int i = 0; i < 4; i++) {
                int r0 = wm * 64 + i * 16 + g;
                const float* xr0 = x + (size_t)(b0 + r0) * XROW + xin * 2;
                const float* xr1 = x + (size_t)(b0 + r0 + 8) * XROW + xin * 2;
                float p00 = __ldg(xr0), p01 = __ldg(xr0 + 1);
                float p10 = __ldg(xr1), p11 = __ldg(xr1 + 1);
#pragma unroll
                for (int jj = 0; jj < 4; jj++) {
                    int c0 = wn * 32 + jj * 8 + 2 * t;
                    float d0 = acc[i][jj][0], d1 = acc[i][jj][1];
                    float d2 = acc[i][jj][2], d3 = acc[i][jj][3];
                    *(float2*)&As[r0 * APITCH + c0]             = make_float2(tf32r(p00 * d0), tf32r(p00 * d1));
                    *(float2*)&As[r0 * APITCH + 128 + c0]       = make_float2(tf32r(p01 * d0), tf32r(p01 * d1));
                    *(float2*)&As[(r0 + 8) * APITCH + c0]       = make_float2(tf32r(p10 * d2), tf32r(p10 * d3));
                    *(float2*)&As[(r0 + 8) * APITCH + 128 + c0] = make_float2(tf32r(p11 * d2), tf32r(p11 * d3));
                }
            }
            // visibility before next step's compute: next quarter-0 sync
        } else {
            float* dst = is_left ? g_left : g_right;
#pragma unroll
            for (int i = 0; i < 4; i++) {
                int r0 = wm * 64 + i * 16 + g;
#pragma unroll
                for (int jj = 0; jj < 4; jj++) {
                    int c0 = wn * 32 + jj * 8 + 2 * t;
                    *(float2*)&dst[(size_t)(b0 + r0) * MDIM + c0]     = make_float2(acc[i][jj][0], acc[i][jj][1]);
                    *(float2*)&dst[(size_t)(b0 + r0 + 8) * MDIM + c0] = make_float2(acc[i][jj][2], acc[i][jj][3]);
                }
            }
        }
    }
}

// ======================= final kernel ======================================
// 128 CTAs x 64 batch rows, 256 threads (v3b structure, passed at 3.4e-4).
__device__ __forceinline__ void compute_slice_f(const float* __restrict__ As,
                                                const float* __restrict__ Wb,
                                                int kb, float acc[2][4][4],
                                                int wm, int wn, int g, int t) {
    const uint32_t* Au = reinterpret_cast<const uint32_t*>(As);
    const uint32_t* Wu = reinterpret_cast<const uint32_t*>(Wb);
#pragma unroll
    for (int kk = 0; kk < 32; kk += 8) {
        uint32_t a[2][4];
#pragma unroll
        for (int i = 0; i < 2; i++) {
            int r = wm * 32 + i * 16 + g;
            int k = kb + kk + t;
            a[i][0] = Au[r * APITCH + k];
            a[i][1] = Au[(r + 8) * APITCH + k];
            a[i][2] = Au[r * APITCH + k + 4];
            a[i][3] = Au[(r + 8) * APITCH + k + 4];
        }
#pragma unroll
        for (int jj = 0; jj < 4; jj++) {
            int cn = wn * 32 + jj * 8 + g;
            uint32_t b0 = Wu[(kk + t) * WPITCH_F + cn];
            uint32_t b1 = Wu[(kk + t + 4) * WPITCH_F + cn];
            mma_tf32(acc[0][jj], a[0], b0, b1);
            mma_tf32(acc[1][jj], a[1], b0, b1);
        }
    }
}

__global__ __launch_bounds__(256, 1)
void final_kernel(const float* __restrict__ x, float* __restrict__ out) {
    extern __shared__ float smem[];
    float* As  = smem;                       // 64 x APITCH
    float* Wb0 = As + 64 * APITCH;
    float* Wb1 = Wb0 + 32 * WPITCH_F;
    float* sR  = Wb1 + 32 * WPITCH_F;        // 64 x RPITCH
    float* sP  = sR + 64 * RPITCH;           // 64 x 4 partials

    const int b0 = blockIdx.x * 64;
    const int tid = threadIdx.x;

    {
        int r = tid >> 2, q = tid & 3;
        const float* xr = x + (size_t)(b0 + r) * XROW + 98 * 2;
        float xl0 = __ldg(xr), xl1 = __ldg(xr + 1);
        for (int m = q * 32; m < q * 32 + 32; m++) {
            float v = g_left[(size_t)(b0 + r) * MDIM + m];
            As[r * APITCH + m]       = tf32r(xl0 * v);
            As[r * APITCH + 128 + m] = tf32r(xl1 * v);
            sR[r * RPITCH + m] = g_right[(size_t)(b0 + r) * MDIM + m];
        }
    }
    __syncthreads();

    const int warp = tid >> 5, lane = tid & 31, g = lane >> 2, t = lane & 3;
    const int wm = warp >> 2, wn = warp & 3;

    for (int l = 0; l < 10; l++) {
        const float* W = g_wlab + (size_t)l * WSTEP;
        float acc[2][4][4];
#pragma unroll
        for (int i = 0; i < 2; i++)
#pragma unroll
            for (int jj = 0; jj < 4; jj++)
#pragma unroll
                for (int q = 0; q < 4; q++) acc[i][jj][q] = 0.f;

        stage32f(Wb0, W, tid);
#pragma unroll 1
        for (int ks = 0; ks < 8; ks++) {
            float* cur = (ks & 1) ? Wb1 : Wb0;
            if (ks < 7) {
                float* nxt = (ks & 1) ? Wb0 : Wb1;
                stage32f(nxt, W + (ks + 1) * 32 * MDIM, tid);
                asm volatile("cp.async.wait_group 1;" ::: "memory");
            } else {
                asm volatile("cp.async.wait_group 0;" ::: "memory");
            }
            __syncthreads();
            compute_slice_f(As, cur, ks * 32, acc, wm, wn, g, t);
            __syncthreads();
        }

#pragma unroll
        for (int i = 0; i < 2; i++) {
            int r0 = wm * 32 + i * 16 + g;
            float p0 = 0.f, p1 = 0.f;
#pragma unroll
            for (int jj = 0; jj < 4; jj++) {
                int c0 = wn * 32 + jj * 8 + 2 * t;
                p0 += acc[i][jj][0] * sR[r0 * RPITCH + c0]
                    + acc[i][jj][1] * sR[r0 * RPITCH + c0 + 1];
                p1 += acc[i][jj][2] * sR[(r0 + 8) * RPITCH + c0]
                    + acc[i][jj][3] * sR[(r0 + 8) * RPITCH + c0 + 1];
            }
            p0 += __shfl_xor_sync(0xffffffffu, p0, 1);
            p0 += __shfl_xor_sync(0xffffffffu, p0, 2);
            p1 += __shfl_xor_sync(0xffffffffu, p1, 1);
            p1 += __shfl_xor_sync(0xffffffffu, p1, 2);
            if (t == 0) {
                sP[r0 * 4 + wn]       = p0;
                sP[(r0 + 8) * 4 + wn] = p1;
            }
        }
        __syncthreads();
        if (tid < 64) {
            float s = sP[tid * 4] + sP[tid * 4 + 1] + sP[tid * 4 + 2] + sP[tid * 4 + 3];
            out[(size_t)(b0 + tid) * 10 + l] = s;
        }
        __syncthreads();
    }
}

// ======================= launch ============================================
extern "C" void kernel_launch(void* const* d_in, const int* in_sizes, int n_in,
                              void* d_out, int out_size) {
    const float *x = nullptr, *w0 = nullptr, *wl = nullptr,
                *wlab = nullptr, *wr = nullptr, *wend = nullptr;
    for (int i = 0; i < n_in; i++) {
        const float* p = (const float*)d_in[i];
        switch (in_sizes[i]) {
            case 3211264: x = p; break;
            case 3178496: wl = p; break;
            case 327680:  wlab = p; break;
            case 3145728: wr = p; break;
            case 256:     if (!w0) w0 = p; else wend = p; break;
            default: break;
        }
    }
    if (!x || !w0 || !wl || !wlab || !wr || !wend) return;

    cudaFuncSetAttribute(scan_kernel,  cudaFuncAttributeMaxDynamicSharedMemorySize, SMEM_SCAN);
    cudaFuncSetAttribute(final_kernel, cudaFuncAttributeMaxDynamicSharedMemorySize, SMEM_FINAL);

    prep_left_k <<<3104, 256>>>(wl);
    prep_right_k<<<3072, 256>>>(wr);
    prep_label_k<<<1280, 256>>>(wlab);
    scan_kernel <<<128, 256, SMEM_SCAN>>>(x, w0, wend);
    final_kernel<<<128, 256, SMEM_FINAL>>>(x, (float*)d_out);
}

// round 10
// speedup vs baseline: 1.0052x; 1.0033x over previous
#include <cuda_runtime.h>
#include <cstdint>

// ---------------------------------------------------------------------------
// QuantumDMRGLayer on GB300 (sm_103a)  —  v5: quarter-step W ring, long phases
//
// left  chain: 97 steps, carry_new(128) = [xi0*c | xi1*c](256) @ Wl[s](256x128)
// right chain: 96 steps (reverse order), inner 128x128 blocks transposed
// final      : out[b,l] = sum_n right[b,n] * ( A_lab[b,:] @ WL_l )[b,n]
//
// All GEMMs: mma.sync.m16n8k8 tf32, fp32 accumulate. Every tf32 operand is
// RN-rounded exactly once (weights in prep kernels, carries in epilogues).
//
// v5 scan: 128 CTAs x 256 thr (1/SM), C-tile 128x128, 8 warps in 2(m) x 4(n)
// grid (64x32 warp tiles). W streamed in 64-k-row quarters (32 KB), 2-deep
// ring -> 5 syncthreads per step instead of 17; long LDS/MMA phases let the
// two warps per SMSP desynchronize and overlap memory against tensor.
// ---------------------------------------------------------------------------

#define BATCH    8192
#define DIMVEC   196
#define XROW     (DIMVEC * 2)
#define MDIM     128
#define NLSTEPS  97
#define NRSTEPS  96
#define WSTEP    (256 * MDIM)      // 32768 floats per step weight matrix
#define QROWS    64                // k-rows per staged quarter
#define QF       (QROWS * MDIM)    // 8192 floats per quarter

#define APITCH   260               // A pitch (mod 32 = 4): conflict-free frags
#define WPITCH   132               // W pitch (mod 32 = 4): conflict-free frags
#define RPITCH   132

static const int SMEM_SCAN  = (128 * APITCH + 2 * QROWS * WPITCH) * 4;                    // 200,704
static const int SMEM_FINAL = (64 * APITCH + 2 * 32 * 136 + 64 * RPITCH + 64 * 4) * 4;    // 136,192
#define WPITCH_F 136               // final kernel keeps v3b 32-row slices

// -------------------- device scratch (static: allocation-free) -------------
__device__ __align__(128) float g_wl  [NLSTEPS * WSTEP];
__device__ __align__(128) float g_wr  [NRSTEPS * WSTEP];   // step-reversed + transposed
__device__ __align__(128) float g_wlab[10 * WSTEP];
__device__ __align__(128) float g_left [BATCH * MDIM];
__device__ __align__(128) float g_right[BATCH * MDIM];

// -------------------- helpers ----------------------------------------------
__device__ __forceinline__ float tf32r(float v) {
    uint32_t u;
    asm("cvt.rna.tf32.f32 %0, %1;" : "=r"(u) : "f"(v));
    return __uint_as_float(u);
}

__device__ __forceinline__ void mma_tf32(float d[4], const uint32_t a[4],
                                         uint32_t b0, uint32_t b1) {
    asm volatile(
        "mma.sync.aligned.m16n8k8.row.col.f32.tf32.tf32.f32 "
        "{%0,%1,%2,%3}, {%4,%5,%6,%7}, {%8,%9}, {%0,%1,%2,%3};\n"
        : "+f"(d[0]), "+f"(d[1]), "+f"(d[2]), "+f"(d[3])
        : "r"(a[0]), "r"(a[1]), "r"(a[2]), "r"(a[3]), "r"(b0), "r"(b1));
}

// Stage one 64(k) x 128(n) fp32 W quarter (32 KB = 2048 x 16B chunks).
__device__ __forceinline__ void stageQ(float* dst, const float* __restrict__ src, int tid) {
#pragma unroll
    for (int i = 0; i < 8; i++) {
        int chunk = tid + i * 256;          // 0..2047
        int row   = chunk >> 5;             // 0..63
        int c     = (chunk & 31) * 4;       // 0..124
        uint32_t s = (uint32_t)__cvta_generic_to_shared(dst + row * WPITCH + c);
        asm volatile("cp.async.cg.shared.global [%0], [%1], 16;"
                     :: "r"(s), "l"(src + row * MDIM + c));
    }
    asm volatile("cp.async.commit_group;" ::: "memory");
}

// Stage one 32(k) x 128(n) slice with pitch 136 (final kernel, v3b layout).
__device__ __forceinline__ void stage32f(float* dst, const float* __restrict__ src, int tid) {
#pragma unroll
    for (int i = 0; i < 4; i++) {
        int chunk = tid + i * 256;
        int row   = chunk >> 5;
        int c     = (chunk & 31) * 4;
        uint32_t s = (uint32_t)__cvta_generic_to_shared(dst + row * WPITCH_F + c);
        asm volatile("cp.async.cg.shared.global [%0], [%1], 16;"
                     :: "r"(s), "l"(src + row * MDIM + c));
    }
    asm volatile("cp.async.commit_group;" ::: "memory");
}

// ======================= prep kernels ======================================
__global__ void prep_left_k(const float* __restrict__ src) {
    int i = (blockIdx.x * 256 + threadIdx.x) * 4;
    float4 v = *reinterpret_cast<const float4*>(src + i);
    v.x = tf32r(v.x); v.y = tf32r(v.y); v.z = tf32r(v.z); v.w = tf32r(v.w);
    *reinterpret_cast<float4*>(g_wl + i) = v;
}

// dst[((j*2+s2)*128+m)*128+n] = rn( src[(((95-j)*2+s2)*128+n)*128+m] )
__global__ void prep_right_k(const float* __restrict__ src) {
    int gid = blockIdx.x * 256 + threadIdx.x;
    int didx = gid * 4;
    int n  = didx & 127;
    int m  = (didx >> 7) & 127;
    int s2 = (didx >> 14) & 1;
    int j  = didx >> 15;
    int s  = 95 - j;
    const float* sb = src + (((size_t)(s * 2 + s2)) * 128) * 128 + m;
    float4 v;
    v.x = tf32r(__ldg(sb + (size_t)(n + 0) * 128));
    v.y = tf32r(__ldg(sb + (size_t)(n + 1) * 128));
    v.z = tf32r(__ldg(sb + (size_t)(n + 2) * 128));
    v.w = tf32r(__ldg(sb + (size_t)(n + 3) * 128));
    *reinterpret_cast<float4*>(g_wr + didx) = v;
}

// dst[l*WSTEP + (p*128+m)*128 + n] = rn( src[((p*128+m)*128+n)*10 + l] )
__global__ void prep_label_k(const float* __restrict__ src) {
    int gid = blockIdx.x * 256 + threadIdx.x;
    int n = gid & 127;
    int m = (gid >> 7) & 127;
    int p = (gid >> 14) & 1;
    int l = gid >> 15;
    int sidx = ((p << 14) | (m << 7) | n) * 10 + l;
    g_wlab[gid] = tf32r(__ldg(src + sidx));
}

// ======================= scan kernel =======================================
// Warp tile 64(m) x 32(n): i in 0..3 (16-row subtiles), jj in 0..3 (8-col).
// acc[4][4][4] = 64 regs. Per 8-k chunk: 16 A-loads + 8 B-loads + 16 MMAs.
__device__ __forceinline__ void compute_quarter(const float* __restrict__ As,
                                                const float* __restrict__ Wb,
                                                int akb, float acc[4][4][4],
                                                int wm, int wn, int g, int t) {
    const uint32_t* Au = reinterpret_cast<const uint32_t*>(As);
    const uint32_t* Wu = reinterpret_cast<const uint32_t*>(Wb);
#pragma unroll
    for (int kk = 0; kk < QROWS; kk += 8) {
        uint32_t a[4][4];
#pragma unroll
        for (int i = 0; i < 4; i++) {
            int r = wm * 64 + i * 16 + g;
            int k = akb + kk + t;
            a[i][0] = Au[r * APITCH + k];
            a[i][1] = Au[(r + 8) * APITCH + k];
            a[i][2] = Au[r * APITCH + k + 4];
            a[i][3] = Au[(r + 8) * APITCH + k + 4];
        }
#pragma unroll
        for (int jj = 0; jj < 4; jj++) {
            int cn = wn * 32 + jj * 8 + g;
            uint32_t b0 = Wu[(kk + t) * WPITCH + cn];
            uint32_t b1 = Wu[(kk + t + 4) * WPITCH + cn];
#pragma unroll
            for (int i = 0; i < 4; i++)
                mma_tf32(acc[i][jj], a[i], b0, b1);
        }
    }
}

__global__ __launch_bounds__(256, 1)
void scan_kernel(const float* __restrict__ x,
                 const float* __restrict__ w0,
                 const float* __restrict__ wend) {
    extern __shared__ float smem[];
    float* As = smem;                              // 128 x APITCH
    float* Wb[2] = { smem + 128 * APITCH,
                     smem + 128 * APITCH + QROWS * WPITCH };

    const bool is_left = blockIdx.x < 64;
    const int  b0 = (blockIdx.x & 63) * 128;
    const int  S  = is_left ? NLSTEPS : NRSTEPS;
    const int  NQ = S * 4;                         // total 64-k quarters
    const float* Wg = is_left ? g_wl : g_wr;
    const float* iw = is_left ? w0 : wend;
    const int tid = threadIdx.x;

    // ---- init: carry = x[iv] @ iw (fp32 FMA), build A for step 0 ----
    {
        int r = tid & 127, q = tid >> 7;           // q in 0..1
        const float* xr = x + (size_t)(b0 + r) * XROW;
        int iv = is_left ? 0 : 195;
        int xi = is_left ? 1 : 194;
        float x0 = xr[iv * 2], x1 = xr[iv * 2 + 1];
        float xi0 = xr[xi * 2], xi1 = xr[xi * 2 + 1];
        for (int m = q * 64; m < q * 64 + 64; m++) {
            float v = x0 * iw[m] + x1 * iw[MDIM + m];
            As[r * APITCH + m]       = tf32r(xi0 * v);
            As[r * APITCH + 128 + m] = tf32r(xi1 * v);
        }
    }

    // prologue: stage quarter 0
    stageQ(Wb[0], Wg, tid);

    const int warp = tid >> 5, lane = tid & 31, g = lane >> 2, t = lane & 3;
    const int wm = warp >> 2, wn = warp & 3;       // wm 0..1, wn 0..3

    for (int j = 0; j < S; j++) {
        float acc[4][4][4];
#pragma unroll
        for (int i = 0; i < 4; i++)
#pragma unroll
            for (int jj = 0; jj < 4; jj++)
#pragma unroll
                for (int q = 0; q < 4; q++) acc[i][jj][q] = 0.f;

#pragma unroll 1
        for (int qs = 0; qs < 4; qs++) {
            int gq = j * 4 + qs;
            asm volatile("cp.async.wait_group 0;" ::: "memory");  // quarter gq landed
            __syncthreads();   // staged data + (qs==0) rebuilt A visible;
                               // all warps past compute(gq-1) -> its buffer free
            if (gq + 1 < NQ)
                stageQ(Wb[(gq + 1) & 1], Wg + (size_t)(gq + 1) * QF, tid);
            compute_quarter(As, Wb[gq & 1], qs * QROWS, acc, wm, wn, g, t);
        }
        __syncthreads();       // all compute done before A overwrite

        if (j + 1 < S) {
            // epilogue: A <- tf32( xi(j+1) * carry_new )
            int xin = is_left ? (2 + j) : (193 - j);
#pragma unroll
            for (int i = 0; i < 4; i++) {
                int r0 = wm * 64 + i * 16 + g;
                const float* xr0 = x + (size_t)(b0 + r0) * XROW + xin * 2;
                const float* xr1 = x + (size_t)(b0 + r0 + 8) * XROW + xin * 2;
                float p00 = __ldg(xr0), p01 = __ldg(xr0 + 1);
                float p10 = __ldg(xr1), p11 = __ldg(xr1 + 1);
#pragma unroll
                for (int jj = 0; jj < 4; jj++) {
                    int c0 = wn * 32 + jj * 8 + 2 * t;
                    float d0 = acc[i][jj][0], d1 = acc[i][jj][1];
                    float d2 = acc[i][jj][2], d3 = acc[i][jj][3];
                    *(float2*)&As[r0 * APITCH + c0]             = make_float2(tf32r(p00 * d0), tf32r(p00 * d1));
                    *(float2*)&As[r0 * APITCH + 128 + c0]       = make_float2(tf32r(p01 * d0), tf32r(p01 * d1));
                    *(float2*)&As[(r0 + 8) * APITCH + c0]       = make_float2(tf32r(p10 * d2), tf32r(p10 * d3));
                    *(float2*)&As[(r0 + 8) * APITCH + 128 + c0] = make_float2(tf32r(p11 * d2), tf32r(p11 * d3));
                }
            }
            // visibility before next step's compute: next quarter-0 sync
        } else {
            float* dst = is_left ? g_left : g_right;
#pragma unroll
            for (int i = 0; i < 4; i++) {
                int r0 = wm * 64 + i * 16 + g;
#pragma unroll
                for (int jj = 0; jj < 4; jj++) {
                    int c0 = wn * 32 + jj * 8 + 2 * t;
                    *(float2*)&dst[(size_t)(b0 + r0) * MDIM + c0]     = make_float2(acc[i][jj][0], acc[i][jj][1]);
                    *(float2*)&dst[(size_t)(b0 + r0 + 8) * MDIM + c0] = make_float2(acc[i][jj][2], acc[i][jj][3]);
                }
            }
        }
    }
}

// ======================= final kernel ======================================
// 128 CTAs x 64 batch rows, 256 threads (v3b structure, passed at 3.4e-4).
__device__ __forceinline__ void compute_slice_f(const float* __restrict__ As,
                                                const float* __restrict__ Wb,
                                                int kb, float acc[2][4][4],
                                                int wm, int wn, int g, int t) {
    const uint32_t* Au = reinterpret_cast<const uint32_t*>(As);
    const uint32_t* Wu = reinterpret_cast<const uint32_t*>(Wb);
#pragma unroll
    for (int kk = 0; kk < 32; kk += 8) {
        uint32_t a[2][4];
#pragma unroll
        for (int i = 0; i < 2; i++) {
            int r = wm * 32 + i * 16 + g;
            int k = kb + kk + t;
            a[i][0] = Au[r * APITCH + k];
            a[i][1] = Au[(r + 8) * APITCH + k];
            a[i][2] = Au[r * APITCH + k + 4];
            a[i][3] = Au[(r + 8) * APITCH + k + 4];
        }
#pragma unroll
        for (int jj = 0; jj < 4; jj++) {
            int cn = wn * 32 + jj * 8 + g;
            uint32_t b0 = Wu[(kk + t) * WPITCH_F + cn];
            uint32_t b1 = Wu[(kk + t + 4) * WPITCH_F + cn];
            mma_tf32(acc[0][jj], a[0], b0, b1);
            mma_tf32(acc[1][jj], a[1], b0, b1);
        }
    }
}

__global__ __launch_bounds__(256, 1)
void final_kernel(const float* __restrict__ x, float* __restrict__ out) {
    extern __shared__ float smem[];
    float* As  = smem;                       // 64 x APITCH
    float* Wb0 = As + 64 * APITCH;
    float* Wb1 = Wb0 + 32 * WPITCH_F;
    float* sR  = Wb1 + 32 * WPITCH_F;        // 64 x RPITCH
    float* sP  = sR + 64 * RPITCH;           // 64 x 4 partials

    const int b0 = blockIdx.x * 64;
    const int tid = threadIdx.x;

    {
        int r = tid >> 2, q = tid & 3;
        const float* xr = x + (size_t)(b0 + r) * XROW + 98 * 2;
        float xl0 = __ldg(xr), xl1 = __ldg(xr + 1);
        for (int m = q * 32; m < q * 32 + 32; m++) {
            float v = g_left[(size_t)(b0 + r) * MDIM + m];
            As[r * APITCH + m]       = tf32r(xl0 * v);
            As[r * APITCH + 128 + m] = tf32r(xl1 * v);
            sR[r * RPITCH + m] = g_right[(size_t)(b0 + r) * MDIM + m];
        }
    }
    __syncthreads();

    const int warp = tid >> 5, lane = tid & 31, g = lane >> 2, t = lane & 3;
    const int wm = warp >> 2, wn = warp & 3;

    for (int l = 0; l < 10; l++) {
        const float* W = g_wlab + (size_t)l * WSTEP;
        float acc[2][4][4];
#pragma unroll
        for (int i = 0; i < 2; i++)
#pragma unroll
            for (int jj = 0; jj < 4; jj++)
#pragma unroll
                for (int q = 0; q < 4; q++) acc[i][jj][q] = 0.f;

        stage32f(Wb0, W, tid);
#pragma unroll 1
        for (int ks = 0; ks < 8; ks++) {
            float* cur = (ks & 1) ? Wb1 : Wb0;
            if (ks < 7) {
                float* nxt = (ks & 1) ? Wb0 : Wb1;
                stage32f(nxt, W + (ks + 1) * 32 * MDIM, tid);
                asm volatile("cp.async.wait_group 1;" ::: "memory");
            } else {
                asm volatile("cp.async.wait_group 0;" ::: "memory");
            }
            __syncthreads();
            compute_slice_f(As, cur, ks * 32, acc, wm, wn, g, t);
            __syncthreads();
        }

#pragma unroll
        for (int i = 0; i < 2; i++) {
            int r0 = wm * 32 + i * 16 + g;
            float p0 = 0.f, p1 = 0.f;
#pragma unroll
            for (int jj = 0; jj < 4; jj++) {
                int c0 = wn * 32 + jj * 8 + 2 * t;
                p0 += acc[i][jj][0] * sR[r0 * RPITCH + c0]
                    + acc[i][jj][1] * sR[r0 * RPITCH + c0 + 1];
                p1 += acc[i][jj][2] * sR[(r0 + 8) * RPITCH + c0]
                    + acc[i][jj][3] * sR[(r0 + 8) * RPITCH + c0 + 1];
            }
            p0 += __shfl_xor_sync(0xffffffffu, p0, 1);
            p0 += __shfl_xor_sync(0xffffffffu, p0, 2);
            p1 += __shfl_xor_sync(0xffffffffu, p1, 1);
            p1 += __shfl_xor_sync(0xffffffffu, p1, 2);
            if (t == 0) {
                sP[r0 * 4 + wn]       = p0;
                sP[(r0 + 8) * 4 + wn] = p1;
            }
        }
        __syncthreads();
        if (tid < 64) {
            float s = sP[tid * 4] + sP[tid * 4 + 1] + sP[tid * 4 + 2] + sP[tid * 4 + 3];
            out[(size_t)(b0 + tid) * 10 + l] = s;
        }
        __syncthreads();
    }
}

// ======================= launch ============================================
extern "C" void kernel_launch(void* const* d_in, const int* in_sizes, int n_in,
                              void* d_out, int out_size) {
    const float *x = nullptr, *w0 = nullptr, *wl = nullptr,
                *wlab = nullptr, *wr = nullptr, *wend = nullptr;
    for (int i = 0; i < n_in; i++) {
        const float* p = (const float*)d_in[i];
        switch (in_sizes[i]) {
            case 3211264: x = p; break;
            case 3178496: wl = p; break;
            case 327680:  wlab = p; break;
            case 3145728: wr = p; break;
            case 256:     if (!w0) w0 = p; else wend = p; break;
            default: break;
        }
    }
    if (!x || !w0 || !wl || !wlab || !wr || !wend) return;

    cudaFuncSetAttribute(scan_kernel,  cudaFuncAttributeMaxDynamicSharedMemorySize, SMEM_SCAN);
    cudaFuncSetAttribute(final_kernel, cudaFuncAttributeMaxDynamicSharedMemorySize, SMEM_FINAL);

    prep_left_k <<<3104, 256>>>(wl);
    prep_right_k<<<3072, 256>>>(wr);
    prep_label_k<<<1280, 256>>>(wlab);
    scan_kernel <<<128, 256, SMEM_SCAN>>>(x, w0, wend);
    final_kernel<<<128, 256, SMEM_FINAL>>>(x, (float*)d_out);
}

// round 13
// speedup vs baseline: 2.1408x; 2.1296x over previous
#include <cuda_runtime.h>
#include <cuda_fp16.h>
#include <cstdint>

// ---------------------------------------------------------------------------
// QuantumDMRGLayer on GB300 (sm_103a) — v7: fp16 mma.sync scan (m16n8k16)
//
// tcgen05 is unavailable (harness PTX targets sm_103, not sm_103a), so the
// scan uses fp16 HMMA at 2x the MAC density of tf32, with ldmatrix fragment
// loads. fp16 has the same 11-bit significand as tf32 -> same rounding walk;
// all values positive and O(1e-4..1e-1), safely inside fp16 normal range.
// fp32 accumulate; weights RN-rounded once (prep), carry RN-rounded once per
// step (epilogue). Final kernel + label prep = proven tf32 mma.sync (R4).
// ---------------------------------------------------------------------------

#define BATCH    8192
#define DIMVEC   196
#define XROW     (DIMVEC * 2)
#define MDIM     128
#define NLSTEPS  97
#define NRSTEPS  96
#define WSTEPH   (256 * MDIM)     // halfs per step weight image
#define SLICEH   (64 * MDIM)      // halfs per 64-k slice

#define APH      264              // A smem pitch (halfs): 528B, mod128B=16 -> ldmatrix conflict-free
#define WPH      136              // W smem pitch (halfs): 272B, mod128B=16 -> conflict-free

// final kernel (proven tf32 path)
#define APITCH   260
#define WPITCH_F 136
#define RPITCH   132
#define WSTEP    (256 * MDIM)

static const int SMEM_SCAN  = (128 * APH + 2 * 64 * WPH) * 2;                             // 102,400
static const int SMEM_FINAL = (64 * APITCH + 2 * 32 * WPITCH_F + 64 * RPITCH + 64*4) * 4; // 136,192

// -------------------- device scratch ---------------------------------------
__device__ __align__(128) __half g_wlh[NLSTEPS * WSTEPH];  // [j][(s2,m)][n]
__device__ __align__(128) __half g_wrh[NRSTEPS * WSTEPH];  // step-reversed + transposed
__device__ __align__(128) float  g_wlab[10 * WSTEP];
__device__ __align__(128) float  g_left [BATCH * MDIM];
__device__ __align__(128) float  g_right[BATCH * MDIM];

// -------------------- helpers ----------------------------------------------
__device__ __forceinline__ float tf32r(float v) {
    uint32_t u; asm("cvt.rna.tf32.f32 %0, %1;" : "=r"(u) : "f"(v));
    return __uint_as_float(u);
}
__device__ __forceinline__ uint32_t smem_u32(const void* p) {
    uint32_t a;
    asm("{ .reg .u64 t; cvta.to.shared.u64 t, %1; cvt.u32.u64 %0, t; }" : "=r"(a) : "l"(p));
    return a;
}
__device__ __forceinline__ void cp16(void* d, const void* s) {
    asm volatile("cp.async.cg.shared.global [%0], [%1], 16;"
                 :: "r"(smem_u32(d)), "l"(s));
}
__device__ __forceinline__ void ldsm4(uint32_t r[4], uint32_t a) {
    asm volatile("ldmatrix.sync.aligned.m8n8.x4.shared.b16 {%0,%1,%2,%3}, [%4];"
                 : "=r"(r[0]),"=r"(r[1]),"=r"(r[2]),"=r"(r[3]) : "r"(a));
}
__device__ __forceinline__ void ldsm4t(uint32_t r[4], uint32_t a) {
    asm volatile("ldmatrix.sync.aligned.m8n8.x4.trans.shared.b16 {%0,%1,%2,%3}, [%4];"
                 : "=r"(r[0]),"=r"(r[1]),"=r"(r[2]),"=r"(r[3]) : "r"(a));
}
__device__ __forceinline__ void mma_h(float d[4], const uint32_t a[4],
                                      uint32_t b0, uint32_t b1) {
    asm volatile("mma.sync.aligned.m16n8k16.row.col.f32.f16.f16.f32 "
        "{%0,%1,%2,%3}, {%4,%5,%6,%7}, {%8,%9}, {%0,%1,%2,%3};\n"
        : "+f"(d[0]),"+f"(d[1]),"+f"(d[2]),"+f"(d[3])
        : "r"(a[0]),"r"(a[1]),"r"(a[2]),"r"(a[3]), "r"(b0),"r"(b1));
}
__device__ __forceinline__ void mma_frag(float d[4], const uint32_t a[4],
                                         uint32_t b0, uint32_t b1) {
    asm volatile("mma.sync.aligned.m16n8k8.row.col.f32.tf32.tf32.f32 "
        "{%0,%1,%2,%3}, {%4,%5,%6,%7}, {%8,%9}, {%0,%1,%2,%3};\n"
        : "+f"(d[0]),"+f"(d[1]),"+f"(d[2]),"+f"(d[3])
        : "r"(a[0]),"r"(a[1]),"r"(a[2]),"r"(a[3]), "r"(b0),"r"(b1));
}

// ======================= prep kernels ======================================
// left: dst linear == src linear; RN to fp16. 2 halfs/thread.
__global__ void prep_left_h(const float* __restrict__ src) {
    int i = (blockIdx.x * 256 + threadIdx.x) * 2;
    float2 v = *reinterpret_cast<const float2*>(src + i);
    *reinterpret_cast<__half2*>(g_wlh + i) = __floats2half2_rn(v.x, v.y);
}
// right: dst[((j*2+s2)*128+m)*128+n] = h(src[(((95-j)*2+s2)*128+n)*128+m])
__global__ void prep_right_h(const float* __restrict__ src) {
    int gid = blockIdx.x * 256 + threadIdx.x;
    int didx = gid * 2;
    int n  = didx & 127;
    int m  = (didx >> 7) & 127;
    int s2 = (didx >> 14) & 1;
    int j  = didx >> 15;
    int s  = 95 - j;
    const float* sb = src + ((size_t)(s * 2 + s2) * 128) * 128 + m;
    float v0 = __ldg(sb + (size_t)(n + 0) * 128);
    float v1 = __ldg(sb + (size_t)(n + 1) * 128);
    *reinterpret_cast<__half2*>(g_wrh + didx) = __floats2half2_rn(v0, v1);
}
// label (fp32 tf32, unchanged): dst[l*WSTEP+(p*128+m)*128+n] = rn(src[((p,m,n)]*10+l])
__global__ void prep_label_k(const float* __restrict__ src) {
    int gid = blockIdx.x * 256 + threadIdx.x;
    int n = gid & 127, m = (gid >> 7) & 127, p = (gid >> 14) & 1, l = gid >> 15;
    g_wlab[gid] = tf32r(__ldg(src + ((p << 14) | (m << 7) | n) * 10 + l));
}

// ======================= scan kernel (fp16) ================================
// 128 CTAs x 256 thr. C-tile 128x128, K=256. 8 warps: wm 0..3 (32 rows),
// wn 0..1 (64 cols). acc[2][8][4]. W in 64-k slices, double-buffered.
// Per 16-k chunk per warp: 2 ldmatrix.x4 (A) + 4 ldmatrix.x4.trans (B) + 16 MMA.
__device__ __forceinline__ void compute_slice_h(uint32_t AsU, uint32_t WbU,
                                                int akb, float acc[2][8][4],
                                                int wm, int wn, int lane) {
    const int lrow = lane & 15, lhi = (lane >> 4) << 3;
#pragma unroll
    for (int kc = 0; kc < 4; kc++) {
        uint32_t a[2][4];
#pragma unroll
        for (int i = 0; i < 2; i++)
            ldsm4(a[i], AsU + (uint32_t)(((wm*32 + i*16 + lrow) * APH
                                          + akb + kc*16 + lhi) * 2));
        uint32_t b[4][4];
#pragma unroll
        for (int p = 0; p < 4; p++)
            ldsm4t(b[p], WbU + (uint32_t)(((kc*16 + lrow) * WPH
                                           + wn*64 + p*16 + lhi) * 2));
#pragma unroll
        for (int i = 0; i < 2; i++)
#pragma unroll
            for (int p = 0; p < 4; p++) {
                mma_h(acc[i][2*p],     a[i], b[p][0], b[p][1]);
                mma_h(acc[i][2*p + 1], a[i], b[p][2], b[p][3]);
            }
    }
}

// stage one 64(k) x 128(n) fp16 slice (16 KB = 1024 x 16B chunks), 4/thread
__device__ __forceinline__ void stageH(__half* dst, const __half* __restrict__ src, int tid) {
#pragma unroll
    for (int i = 0; i < 4; i++) {
        int chunk = tid + i * 256;
        int row = chunk >> 4, c = (chunk & 15) * 8;
        cp16(dst + row * WPH + c, src + row * MDIM + c);
    }
    asm volatile("cp.async.commit_group;" ::: "memory");
}

__global__ __launch_bounds__(256, 1)
void scan_kernel(const float* __restrict__ x,
                 const float* __restrict__ w0,
                 const float* __restrict__ wend) {
    extern __shared__ __half smh[];
    __half* Ah = smh;                               // 128 x APH
    __half* Wb[2] = { smh + 128 * APH, smh + 128 * APH + 64 * WPH };
    const uint32_t AsU = smem_u32(Ah);
    const uint32_t WbU[2] = { smem_u32(Wb[0]), smem_u32(Wb[1]) };

    const bool is_left = blockIdx.x < 64;
    const int  b0 = (blockIdx.x & 63) * 128;
    const int  S  = is_left ? NLSTEPS : NRSTEPS;
    const int  NS = S * 4;                          // 64-k slices total
    const __half* Wg = is_left ? g_wlh : g_wrh;
    const float* iw = is_left ? w0 : wend;
    const int tid = threadIdx.x;

    // ---- init: carry = x[iv] @ iw (fp32), A = h(xi * carry) ----
    {
        int r = tid & 127, q = tid >> 7;            // q in 0..1
        const float* xr = x + (size_t)(b0 + r) * XROW;
        int iv = is_left ? 0 : 195, xi = is_left ? 1 : 194;
        float x0 = xr[iv*2], x1 = xr[iv*2+1], xi0 = xr[xi*2], xi1 = xr[xi*2+1];
        for (int m = q * 64; m < q * 64 + 64; m++) {
            float v = x0 * iw[m] + x1 * iw[MDIM + m];
            Ah[r * APH + m]       = __float2half_rn(xi0 * v);
            Ah[r * APH + 128 + m] = __float2half_rn(xi1 * v);
        }
    }

    stageH(Wb[0], Wg, tid);                         // slice 0
    __syncthreads();

    const int warp = tid >> 5, lane = tid & 31, g = lane >> 2, t = lane & 3;
    const int wm = warp >> 1, wn = warp & 1;        // wm 0..3, wn 0..1

    for (int j = 0; j < S; j++) {
        float acc[2][8][4];
#pragma unroll
        for (int i = 0; i < 2; i++)
#pragma unroll
            for (int jj = 0; jj < 8; jj++)
#pragma unroll
                for (int q = 0; q < 4; q++) acc[i][jj][q] = 0.f;

#pragma unroll 1
        for (int c = 0; c < 4; c++) {
            int gs = j * 4 + c;
            if (gs + 1 < NS) {                      // stage next into buf of gs-1 (free)
                stageH(Wb[(gs + 1) & 1], Wg + (size_t)(gs + 1) * SLICEH, tid);
                asm volatile("cp.async.wait_group 1;" ::: "memory");  // gs landed
            } else {
                asm volatile("cp.async.wait_group 0;" ::: "memory");
            }
            __syncthreads();       // slice gs (+ rebuilt A when c==0) visible
            compute_slice_h(AsU, WbU[gs & 1], c * 64, acc, wm, wn, lane);
            __syncthreads();       // all reads done before buffer/A reuse
        }

        if (j + 1 < S) {
            // epilogue: A <- h( xi(j+1) * carry_new )
            int xin = is_left ? (2 + j) : (193 - j);
#pragma unroll
            for (int i = 0; i < 2; i++) {
                int r0 = wm * 32 + i * 16 + g;
                const float* xr0 = x + (size_t)(b0 + r0) * XROW + xin * 2;
                const float* xr1 = x + (size_t)(b0 + r0 + 8) * XROW + xin * 2;
                float p00 = __ldg(xr0), p01 = __ldg(xr0 + 1);
                float p10 = __ldg(xr1), p11 = __ldg(xr1 + 1);
#pragma unroll
                for (int jj = 0; jj < 8; jj++) {
                    int c0 = wn * 64 + jj * 8 + 2 * t;
                    float d0 = acc[i][jj][0], d1 = acc[i][jj][1];
                    float d2 = acc[i][jj][2], d3 = acc[i][jj][3];
                    *(__half2*)(Ah + r0 * APH + c0)             = __floats2half2_rn(p00*d0, p00*d1);
                    *(__half2*)(Ah + r0 * APH + 128 + c0)       = __floats2half2_rn(p01*d0, p01*d1);
                    *(__half2*)(Ah + (r0 + 8) * APH + c0)       = __floats2half2_rn(p10*d2, p10*d3);
                    *(__half2*)(Ah + (r0 + 8) * APH + 128 + c0) = __floats2half2_rn(p11*d2, p11*d3);
                }
            }
            // visibility before next compute: sync inside next slice iter
        } else {
            float* dst = is_left ? g_left : g_right;
#pragma unroll
            for (int i = 0; i < 2; i++) {
                int r0 = wm * 32 + i * 16 + g;
#pragma unroll
                for (int jj = 0; jj < 8; jj++) {
                    int c0 = wn * 64 + jj * 8 + 2 * t;
                    *(float2*)&dst[(size_t)(b0 + r0) * MDIM + c0]     = make_float2(acc[i][jj][0], acc[i][jj][1]);
                    *(float2*)&dst[(size_t)(b0 + r0 + 8) * MDIM + c0] = make_float2(acc[i][jj][2], acc[i][jj][3]);
                }
            }
        }
    }
}

// ======================= final kernel (tf32, proven) =======================
__device__ __forceinline__ void stage32f(float* dst, const float* __restrict__ src, int tid) {
#pragma unroll
    for (int i = 0; i < 4; i++) {
        int chunk = tid + i * 256, row = chunk >> 5, cc = (chunk & 31) * 4;
        cp16(dst + row * WPITCH_F + cc, src + row * MDIM + cc);
    }
    asm volatile("cp.async.commit_group;" ::: "memory");
}

__device__ __forceinline__ void compute_slice_f(const float* __restrict__ As,
                                                const float* __restrict__ Wb,
                                                int kb, float acc[2][4][4],
                                                int wm, int wn, int g, int t) {
    const uint32_t* Au = (const uint32_t*)As;
    const uint32_t* Wu = (const uint32_t*)Wb;
#pragma unroll
    for (int kk = 0; kk < 32; kk += 8) {
        uint32_t a[2][4];
#pragma unroll
        for (int i = 0; i < 2; i++) {
            int rr = wm * 32 + i * 16 + g, k = kb + kk + t;
            a[i][0] = Au[rr * APITCH + k];
            a[i][1] = Au[(rr + 8) * APITCH + k];
            a[i][2] = Au[rr * APITCH + k + 4];
            a[i][3] = Au[(rr + 8) * APITCH + k + 4];
        }
#pragma unroll
        for (int jj = 0; jj < 4; jj++) {
            int cn = wn * 32 + jj * 8 + g;
            uint32_t b0 = Wu[(kk + t) * WPITCH_F + cn];
            uint32_t b1 = Wu[(kk + t + 4) * WPITCH_F + cn];
            mma_frag(acc[0][jj], a[0], b0, b1);
            mma_frag(acc[1][jj], a[1], b0, b1);
        }
    }
}

__global__ __launch_bounds__(256, 1)
void final_kernel(const float* __restrict__ x, float* __restrict__ out) {
    extern __shared__ float smemf[];
    float* As  = smemf;
    float* Wb0 = As + 64 * APITCH;
    float* Wb1 = Wb0 + 32 * WPITCH_F;
    float* sR  = Wb1 + 32 * WPITCH_F;
    float* sP  = sR + 64 * RPITCH;

    const int b0 = blockIdx.x * 64, tid = threadIdx.x;
    {
        int rr = tid >> 2, q = tid & 3;
        const float* xr = x + (size_t)(b0 + rr) * XROW + 98 * 2;
        float xl0 = __ldg(xr), xl1 = __ldg(xr + 1);
        for (int m = q * 32; m < q * 32 + 32; m++) {
            float v = g_left[(size_t)(b0 + rr) * MDIM + m];
            As[rr * APITCH + m]       = tf32r(xl0 * v);
            As[rr * APITCH + 128 + m] = tf32r(xl1 * v);
            sR[rr * RPITCH + m] = g_right[(size_t)(b0 + rr) * MDIM + m];
        }
    }
    __syncthreads();

    const int warp = tid >> 5, lane = tid & 31, g = lane >> 2, t = lane & 3;
    const int wm = warp >> 2, wn = warp & 3;

    for (int l = 0; l < 10; l++) {
        const float* W = g_wlab + (size_t)l * WSTEP;
        float acc[2][4][4];
#pragma unroll
        for (int i = 0; i < 2; i++)
#pragma unroll
            for (int jj = 0; jj < 4; jj++)
#pragma unroll
                for (int q = 0; q < 4; q++) acc[i][jj][q] = 0.f;

        stage32f(Wb0, W, tid);
#pragma unroll 1
        for (int ks = 0; ks < 8; ks++) {
            float* cur = (ks & 1) ? Wb1 : Wb0;
            if (ks < 7) {
                stage32f((ks & 1) ? Wb0 : Wb1, W + (ks + 1) * 32 * MDIM, tid);
                asm volatile("cp.async.wait_group 1;" ::: "memory");
            } else {
                asm volatile("cp.async.wait_group 0;" ::: "memory");
            }
            __syncthreads();
            compute_slice_f(As, cur, ks * 32, acc, wm, wn, g, t);
            __syncthreads();
        }
#pragma unroll
        for (int i = 0; i < 2; i++) {
            int r0 = wm * 32 + i * 16 + g;
            float p0 = 0.f, p1 = 0.f;
#pragma unroll
            for (int jj = 0; jj < 4; jj++) {
                int c0 = wn * 32 + jj * 8 + 2 * t;
                p0 += acc[i][jj][0] * sR[r0 * RPITCH + c0]
                    + acc[i][jj][1] * sR[r0 * RPITCH + c0 + 1];
                p1 += acc[i][jj][2] * sR[(r0 + 8) * RPITCH + c0]
                    + acc[i][jj][3] * sR[(r0 + 8) * RPITCH + c0 + 1];
            }
            p0 += __shfl_xor_sync(0xffffffffu, p0, 1);
            p0 += __shfl_xor_sync(0xffffffffu, p0, 2);
            p1 += __shfl_xor_sync(0xffffffffu, p1, 1);
            p1 += __shfl_xor_sync(0xffffffffu, p1, 2);
            if (t == 0) { sP[r0 * 4 + wn] = p0; sP[(r0 + 8) * 4 + wn] = p1; }
        }
        __syncthreads();
        if (tid < 64)
            out[(size_t)(b0 + tid) * 10 + l] =
                sP[tid * 4] + sP[tid * 4 + 1] + sP[tid * 4 + 2] + sP[tid * 4 + 3];
        __syncthreads();
    }
}

// ======================= launch ============================================
extern "C" void kernel_launch(void* const* d_in, const int* in_sizes, int n_in,
                              void* d_out, int out_size) {
    const float *x = nullptr, *w0 = nullptr, *wl = nullptr,
                *wlab = nullptr, *wr = nullptr, *wend = nullptr;
    for (int i = 0; i < n_in; i++) {
        const float* p = (const float*)d_in[i];
        switch (in_sizes[i]) {
            case 3211264: x = p; break;
            case 3178496: wl = p; break;
            case 327680:  wlab = p; break;
            case 3145728: wr = p; break;
            case 256:     if (!w0) w0 = p; else wend = p; break;
            default: break;
        }
    }
    if (!x || !w0 || !wl || !wlab || !wr || !wend) return;

    cudaFuncSetAttribute(scan_kernel,  cudaFuncAttributeMaxDynamicSharedMemorySize, SMEM_SCAN);
    cudaFuncSetAttribute(final_kernel, cudaFuncAttributeMaxDynamicSharedMemorySize, SMEM_FINAL);

    prep_left_h <<<6208, 256>>>(wl);    // 97*32768/2/256
    prep_right_h<<<6144, 256>>>(wr);    // 96*32768/2/256
    prep_label_k<<<1280, 256>>>(wlab);
    scan_kernel <<<128, 256, SMEM_SCAN>>>(x, w0, wend);
    final_kernel<<<128, 256, SMEM_FINAL>>>(x, (float*)d_out);
}

// round 15
// speedup vs baseline: 2.2914x; 1.0704x over previous
#include <cuda_runtime.h>
#include <cuda_fp16.h>
#include <cstdint>

// ---------------------------------------------------------------------------
// QuantumDMRGLayer on GB300 (sm_103a) — v8: fp16 scan, full-step W double buf
//
// Scan: fp16 m16n8k16 HMMA (same 11-bit significand as tf32 -> same rounding
// walk; values positive, O(1e-4..1e-1), inside fp16 range), fp32 accumulate,
// ldmatrix fragments. v8: whole 64 KB step-W double-buffered -> 2 syncthreads
// per step (was 8); one long compute phase per step lets warps drift and
// overlap LDS against HMMA. Final kernel + label prep = proven tf32 path.
// ---------------------------------------------------------------------------

#define BATCH    8192
#define DIMVEC   196
#define XROW     (DIMVEC * 2)
#define MDIM     128
#define NLSTEPS  97
#define NRSTEPS  96
#define WSTEPH   (256 * MDIM)     // halfs per step weight image

#define APH      264              // A smem pitch (halfs): 528B ≡16B mod 128B -> conflict-free
#define WPH      136              // W smem pitch (halfs): 272B ≡16B mod 128B -> conflict-free

// final kernel (proven tf32 path)
#define APITCH   260
#define WPITCH_F 136
#define RPITCH   132
#define WSTEP    (256 * MDIM)

static const int SMEM_SCAN  = (128 * APH + 2 * 256 * WPH) * 2;                            // 206,848
static const int SMEM_FINAL = (64 * APITCH + 2 * 32 * WPITCH_F + 64 * RPITCH + 64*4) * 4; // 136,192

// -------------------- device scratch ---------------------------------------
__device__ __align__(128) __half g_wlh[NLSTEPS * WSTEPH];  // [j][(s2,m)][n]
__device__ __align__(128) __half g_wrh[NRSTEPS * WSTEPH];  // step-reversed + transposed
__device__ __align__(128) float  g_wlab[10 * WSTEP];
__device__ __align__(128) float  g_left [BATCH * MDIM];
__device__ __align__(128) float  g_right[BATCH * MDIM];

// -------------------- helpers ----------------------------------------------
__device__ __forceinline__ float tf32r(float v) {
    uint32_t u; asm("cvt.rna.tf32.f32 %0, %1;" : "=r"(u) : "f"(v));
    return __uint_as_float(u);
}
__device__ __forceinline__ uint32_t smem_u32(const void* p) {
    uint32_t a;
    asm("{ .reg .u64 t; cvta.to.shared.u64 t, %1; cvt.u32.u64 %0, t; }" : "=r"(a) : "l"(p));
    return a;
}
__device__ __forceinline__ void cp16(void* d, const void* s) {
    asm volatile("cp.async.cg.shared.global [%0], [%1], 16;"
                 :: "r"(smem_u32(d)), "l"(s));
}
__device__ __forceinline__ void ldsm4(uint32_t r[4], uint32_t a) {
    asm volatile("ldmatrix.sync.aligned.m8n8.x4.shared.b16 {%0,%1,%2,%3}, [%4];"
                 : "=r"(r[0]),"=r"(r[1]),"=r"(r[2]),"=r"(r[3]) : "r"(a));
}
__device__ __forceinline__ void ldsm4t(uint32_t r[4], uint32_t a) {
    asm volatile("ldmatrix.sync.aligned.m8n8.x4.trans.shared.b16 {%0,%1,%2,%3}, [%4];"
                 : "=r"(r[0]),"=r"(r[1]),"=r"(r[2]),"=r"(r[3]) : "r"(a));
}
__device__ __forceinline__ void mma_h(float d[4], const uint32_t a[4],
                                      uint32_t b0, uint32_t b1) {
    asm volatile("mma.sync.aligned.m16n8k16.row.col.f32.f16.f16.f32 "
        "{%0,%1,%2,%3}, {%4,%5,%6,%7}, {%8,%9}, {%0,%1,%2,%3};\n"
        : "+f"(d[0]),"+f"(d[1]),"+f"(d[2]),"+f"(d[3])
        : "r"(a[0]),"r"(a[1]),"r"(a[2]),"r"(a[3]), "r"(b0),"r"(b1));
}
__device__ __forceinline__ void mma_frag(float d[4], const uint32_t a[4],
                                         uint32_t b0, uint32_t b1) {
    asm volatile("mma.sync.aligned.m16n8k8.row.col.f32.tf32.tf32.f32 "
        "{%0,%1,%2,%3}, {%4,%5,%6,%7}, {%8,%9}, {%0,%1,%2,%3};\n"
        : "+f"(d[0]),"+f"(d[1]),"+f"(d[2]),"+f"(d[3])
        : "r"(a[0]),"r"(a[1]),"r"(a[2]),"r"(a[3]), "r"(b0),"r"(b1));
}

// ======================= prep kernels ======================================
__global__ void prep_left_h(const float* __restrict__ src) {
    int i = (blockIdx.x * 256 + threadIdx.x) * 2;
    float2 v = *reinterpret_cast<const float2*>(src + i);
    *reinterpret_cast<__half2*>(g_wlh + i) = __floats2half2_rn(v.x, v.y);
}
// dst[((j*2+s2)*128+m)*128+n] = h(src[(((95-j)*2+s2)*128+n)*128+m])
__global__ void prep_right_h(const float* __restrict__ src) {
    int gid = blockIdx.x * 256 + threadIdx.x;
    int didx = gid * 2;
    int n  = didx & 127;
    int m  = (didx >> 7) & 127;
    int s2 = (didx >> 14) & 1;
    int j  = didx >> 15;
    int s  = 95 - j;
    const float* sb = src + ((size_t)(s * 2 + s2) * 128) * 128 + m;
    float v0 = __ldg(sb + (size_t)(n + 0) * 128);
    float v1 = __ldg(sb + (size_t)(n + 1) * 128);
    *reinterpret_cast<__half2*>(g_wrh + didx) = __floats2half2_rn(v0, v1);
}
__global__ void prep_label_k(const float* __restrict__ src) {
    int gid = blockIdx.x * 256 + threadIdx.x;
    int n = gid & 127, m = (gid >> 7) & 127, p = (gid >> 14) & 1, l = gid >> 15;
    g_wlab[gid] = tf32r(__ldg(src + ((p << 14) | (m << 7) | n) * 10 + l));
}

// ======================= scan kernel (fp16, v8) ============================
// 128 CTAs x 256 thr. C-tile 128x128, K=256. 8 warps: wm 0..3 (32 rows),
// wn 0..1 (64 cols). acc[2][8][4]. Full-step W (256 x WPH) double-buffered.
__device__ __forceinline__ void compute_step(uint32_t AsU, uint32_t WbU,
                                             float acc[2][8][4],
                                             int wm, int wn, int lane) {
    const int lrow = lane & 15, lhi = (lane >> 4) << 3;
#pragma unroll
    for (int kc = 0; kc < 16; kc++) {
        uint32_t a[2][4];
#pragma unroll
        for (int i = 0; i < 2; i++)
            ldsm4(a[i], AsU + (uint32_t)(((wm*32 + i*16 + lrow) * APH
                                          + kc*16 + lhi) * 2));
        uint32_t b[4][4];
#pragma unroll
        for (int p = 0; p < 4; p++)
            ldsm4t(b[p], WbU + (uint32_t)(((kc*16 + lrow) * WPH
                                           + wn*64 + p*16 + lhi) * 2));
#pragma unroll
        for (int i = 0; i < 2; i++)
#pragma unroll
            for (int p = 0; p < 4; p++) {
                mma_h(acc[i][2*p],     a[i], b[p][0], b[p][1]);
                mma_h(acc[i][2*p + 1], a[i], b[p][2], b[p][3]);
            }
    }
}

// stage one full step: 256(k) x 128(n) fp16 (64 KB = 4096 x 16B), 16/thread
__device__ __forceinline__ void stageF(__half* dst, const __half* __restrict__ src, int tid) {
#pragma unroll
    for (int i = 0; i < 16; i++) {
        int chunk = tid + i * 256;          // 0..4095
        int row = chunk >> 4, c = (chunk & 15) * 8;
        cp16(dst + row * WPH + c, src + row * MDIM + c);
    }
    asm volatile("cp.async.commit_group;" ::: "memory");
}

__global__ __launch_bounds__(256, 1)
void scan_kernel(const float* __restrict__ x,
                 const float* __restrict__ w0,
                 const float* __restrict__ wend) {
    extern __shared__ __half smh[];
    __half* Ah = smh;                               // 128 x APH
    __half* Wb[2] = { smh + 128 * APH, smh + 128 * APH + 256 * WPH };
    const uint32_t AsU = smem_u32(Ah);
    const uint32_t WbU[2] = { smem_u32(Wb[0]), smem_u32(Wb[1]) };

    const bool is_left = blockIdx.x < 64;
    const int  b0 = (blockIdx.x & 63) * 128;
    const int  S  = is_left ? NLSTEPS : NRSTEPS;
    const __half* Wg = is_left ? g_wlh : g_wrh;
    const float* iw = is_left ? w0 : wend;
    const int tid = threadIdx.x;

    // ---- init: carry = x[iv] @ iw (fp32), A = h(xi * carry) ----
    {
        int r = tid & 127, q = tid >> 7;            // q in 0..1
        const float* xr = x + (size_t)(b0 + r) * XROW;
        int iv = is_left ? 0 : 195, xi = is_left ? 1 : 194;
        float x0 = xr[iv*2], x1 = xr[iv*2+1], xi0 = xr[xi*2], xi1 = xr[xi*2+1];
        for (int m = q * 64; m < q * 64 + 64; m++) {
            float v = x0 * iw[m] + x1 * iw[MDIM + m];
            Ah[r * APH + m]       = __float2half_rn(xi0 * v);
            Ah[r * APH + 128 + m] = __float2half_rn(xi1 * v);
        }
    }

    // prologue: stage steps 0 and 1 (one commit group each)
    stageF(Wb[0], Wg, tid);
    if (S > 1) stageF(Wb[1], Wg + WSTEPH, tid);

    const int warp = tid >> 5, lane = tid & 31, g = lane >> 2, t = lane & 3;
    const int wm = warp >> 1, wn = warp & 1;        // wm 0..3, wn 0..1

    for (int j = 0; j < S; j++) {
        float acc[2][8][4];
#pragma unroll
        for (int i = 0; i < 2; i++)
#pragma unroll
            for (int jj = 0; jj < 8; jj++)
#pragma unroll
                for (int q = 0; q < 4; q++) acc[i][jj][q] = 0.f;

        // groups in flight: {j, j+1 (if staged)} -> wait for step j
        if (j + 1 < S) asm volatile("cp.async.wait_group 1;" ::: "memory");
        else           asm volatile("cp.async.wait_group 0;" ::: "memory");
        __syncthreads();           // W[j] + rebuilt A visible to all warps

        compute_step(AsU, WbU[j & 1], acc, wm, wn, lane);
        __syncthreads();           // all warps done reading A and Wb[j&1]

        if (j + 2 < S)             // refill the just-freed buffer
            stageF(Wb[j & 1], Wg + (size_t)(j + 2) * WSTEPH, tid);

        if (j + 1 < S) {
            // epilogue: A <- h( xi(j+1) * carry_new )
            int xin = is_left ? (2 + j) : (193 - j);
#pragma unroll
            for (int i = 0; i < 2; i++) {
                int r0 = wm * 32 + i * 16 + g;
                const float* xr0 = x + (size_t)(b0 + r0) * XROW + xin * 2;
                const float* xr1 = x + (size_t)(b0 + r0 + 8) * XROW + xin * 2;
                float p00 = __ldg(xr0), p01 = __ldg(xr0 + 1);
                float p10 = __ldg(xr1), p11 = __ldg(xr1 + 1);
#pragma unroll
                for (int jj = 0; jj < 8; jj++) {
                    int c0 = wn * 64 + jj * 8 + 2 * t;
                    float d0 = acc[i][jj][0], d1 = acc[i][jj][1];
                    float d2 = acc[i][jj][2], d3 = acc[i][jj][3];
                    *(__half2*)(Ah + r0 * APH + c0)             = __floats2half2_rn(p00*d0, p00*d1);
                    *(__half2*)(Ah + r0 * APH + 128 + c0)       = __floats2half2_rn(p01*d0, p01*d1);
                    *(__half2*)(Ah + (r0 + 8) * APH + c0)       = __floats2half2_rn(p10*d2, p10*d3);
                    *(__half2*)(Ah + (r0 + 8) * APH + 128 + c0) = __floats2half2_rn(p11*d2, p11*d3);
                }
            }
            // rebuilt A published by next step's top-of-loop __syncthreads
        } else {
            float* dst = is_left ? g_left : g_right;
#pragma unroll
            for (int i = 0; i < 2; i++) {
                int r0 = wm * 32 + i * 16 + g;
#pragma unroll
                for (int jj = 0; jj < 8; jj++) {
                    int c0 = wn * 64 + jj * 8 + 2 * t;
                    *(float2*)&dst[(size_t)(b0 + r0) * MDIM + c0]     = make_float2(acc[i][jj][0], acc[i][jj][1]);
                    *(float2*)&dst[(size_t)(b0 + r0 + 8) * MDIM + c0] = make_float2(acc[i][jj][2], acc[i][jj][3]);
                }
            }
        }
    }
}

// ======================= final kernel (tf32, proven) =======================
__device__ __forceinline__ void stage32f(float* dst, const float* __restrict__ src, int tid) {
#pragma unroll
    for (int i = 0; i < 4; i++) {
        int chunk = tid + i * 256, row = chunk >> 5, cc = (chunk & 31) * 4;
        cp16(dst + row * WPITCH_F + cc, src + row * MDIM + cc);
    }
    asm volatile("cp.async.commit_group;" ::: "memory");
}

__device__ __forceinline__ void compute_slice_f(const float* __restrict__ As,
                                                const float* __restrict__ Wb,
                                                int kb, float acc[2][4][4],
                                                int wm, int wn, int g, int t) {
    const uint32_t* Au = (const uint32_t*)As;
    const uint32_t* Wu = (const uint32_t*)Wb;
#pragma unroll
    for (int kk = 0; kk < 32; kk += 8) {
        uint32_t a[2][4];
#pragma unroll
        for (int i = 0; i < 2; i++) {
            int rr = wm * 32 + i * 16 + g, k = kb + kk + t;
            a[i][0] = Au[rr * APITCH + k];
            a[i][1] = Au[(rr + 8) * APITCH + k];
            a[i][2] = Au[rr * APITCH + k + 4];
            a[i][3] = Au[(rr + 8) * APITCH + k + 4];
        }
#pragma unroll
        for (int jj = 0; jj < 4; jj++) {
            int cn = wn * 32 + jj * 8 + g;
            uint32_t b0 = Wu[(kk + t) * WPITCH_F + cn];
            uint32_t b1 = Wu[(kk + t + 4) * WPITCH_F + cn];
            mma_frag(acc[0][jj], a[0], b0, b1);
            mma_frag(acc[1][jj], a[1], b0, b1);
        }
    }
}

__global__ __launch_bounds__(256, 1)
void final_kernel(const float* __restrict__ x, float* __restrict__ out) {
    extern __shared__ float smemf[];
    float* As  = smemf;
    float* Wb0 = As + 64 * APITCH;
    float* Wb1 = Wb0 + 32 * WPITCH_F;
    float* sR  = Wb1 + 32 * WPITCH_F;
    float* sP  = sR + 64 * RPITCH;

    const int b0 = blockIdx.x * 64, tid = threadIdx.x;
    {
        int rr = tid >> 2, q = tid & 3;
        const float* xr = x + (size_t)(b0 + rr) * XROW + 98 * 2;
        float xl0 = __ldg(xr), xl1 = __ldg(xr + 1);
        for (int m = q * 32; m < q * 32 + 32; m++) {
            float v = g_left[(size_t)(b0 + rr) * MDIM + m];
            As[rr * APITCH + m]       = tf32r(xl0 * v);
            As[rr * APITCH + 128 + m] = tf32r(xl1 * v);
            sR[rr * RPITCH + m] = g_right[(size_t)(b0 + rr) * MDIM + m];
        }
    }
    __syncthreads();

    const int warp = tid >> 5, lane = tid & 31, g = lane >> 2, t = lane & 3;
    const int wm = warp >> 2, wn = warp & 3;

    for (int l = 0; l < 10; l++) {
        const float* W = g_wlab + (size_t)l * WSTEP;
        float acc[2][4][4];
#pragma unroll
        for (int i = 0; i < 2; i++)
#pragma unroll
            for (int jj = 0; jj < 4; jj++)
#pragma unroll
                for (int q = 0; q < 4; q++) acc[i][jj][q] = 0.f;

        stage32f(Wb0, W, tid);
#pragma unroll 1
        for (int ks = 0; ks < 8; ks++) {
            float* cur = (ks & 1) ? Wb1 : Wb0;
            if (ks < 7) {
                stage32f((ks & 1) ? Wb0 : Wb1, W + (ks + 1) * 32 * MDIM, tid);
                asm volatile("cp.async.wait_group 1;" ::: "memory");
            } else {
                asm volatile("cp.async.wait_group 0;" ::: "memory");
            }
            __syncthreads();
            compute_slice_f(As, cur, ks * 32, acc, wm, wn, g, t);
            __syncthreads();
        }
#pragma unroll
        for (int i = 0; i < 2; i++) {
            int r0 = wm * 32 + i * 16 + g;
            float p0 = 0.f, p1 = 0.f;
#pragma unroll
            for (int jj = 0; jj < 4; jj++) {
                int c0 = wn * 32 + jj * 8 + 2 * t;
                p0 += acc[i][jj][0] * sR[r0 * RPITCH + c0]
                    + acc[i][jj][1] * sR[r0 * RPITCH + c0 + 1];
                p1 += acc[i][jj][2] * sR[(r0 + 8) * RPITCH + c0]
                    + acc[i][jj][3] * sR[(r0 + 8) * RPITCH + c0 + 1];
            }
            p0 += __shfl_xor_sync(0xffffffffu, p0, 1);
            p0 += __shfl_xor_sync(0xffffffffu, p0, 2);
            p1 += __shfl_xor_sync(0xffffffffu, p1, 1);
            p1 += __shfl_xor_sync(0xffffffffu, p1, 2);
            if (t == 0) { sP[r0 * 4 + wn] = p0; sP[(r0 + 8) * 4 + wn] = p1; }
        }
        __syncthreads();
        if (tid < 64)
            out[(size_t)(b0 + tid) * 10 + l] =
                sP[tid * 4] + sP[tid * 4 + 1] + sP[tid * 4 + 2] + sP[tid * 4 + 3];
        __syncthreads();
    }
}

// ======================= launch ============================================
extern "C" void kernel_launch(void* const* d_in, const int* in_sizes, int n_in,
                              void* d_out, int out_size) {
    const float *x = nullptr, *w0 = nullptr, *wl = nullptr,
                *wlab = nullptr, *wr = nullptr, *wend = nullptr;
    for (int i = 0; i < n_in; i++) {
        const float* p = (const float*)d_in[i];
        switch (in_sizes[i]) {
            case 3211264: x = p; break;
            case 3178496: wl = p; break;
            case 327680:  wlab = p; break;
            case 3145728: wr = p; break;
            case 256:     if (!w0) w0 = p; else wend = p; break;
            default: break;
        }
    }
    if (!x || !w0 || !wl || !wlab || !wr || !wend) return;

    cudaFuncSetAttribute(scan_kernel,  cudaFuncAttributeMaxDynamicSharedMemorySize, SMEM_SCAN);
    cudaFuncSetAttribute(final_kernel, cudaFuncAttributeMaxDynamicSharedMemorySize, SMEM_FINAL);

    prep_left_h <<<6208, 256>>>(wl);
    prep_right_h<<<6144, 256>>>(wr);
    prep_label_k<<<1280, 256>>>(wlab);
    scan_kernel <<<128, 256, SMEM_SCAN>>>(x, w0, wend);
    final_kernel<<<128, 256, SMEM_FINAL>>>(x, (float*)d_out);
}

// round 17
// speedup vs baseline: 2.4118x; 1.0525x over previous
#include <cuda_runtime.h>
#include <cuda_fp16.h>
#include <cstdint>

// ---------------------------------------------------------------------------
// QuantumDMRGLayer on GB300 (sm_103a) — v9: fp16 scan, pair-barrier epilogue
//
// v8 + (1) compute->epilogue hazard handled by 64-thread named barriers
// (A rows are pair-private to the two warps sharing wm) so pairs drift and
// epilogues overlap other pairs' HMMA; (2) xi scalars prefetched before
// compute; (3) fragment double-buffering inside compute_step.
// Final kernel + label prep = proven tf32 path.
// ---------------------------------------------------------------------------

#define BATCH    8192
#define DIMVEC   196
#define XROW     (DIMVEC * 2)
#define MDIM     128
#define NLSTEPS  97
#define NRSTEPS  96
#define WSTEPH   (256 * MDIM)     // halfs per step weight image

#define APH      264              // A smem pitch (halfs): 528B ≡16B mod 128B -> conflict-free
#define WPH      136              // W smem pitch (halfs): 272B ≡16B mod 128B -> conflict-free

// final kernel (proven tf32 path)
#define APITCH   260
#define WPITCH_F 136
#define RPITCH   132
#define WSTEP    (256 * MDIM)

static const int SMEM_SCAN  = (128 * APH + 2 * 256 * WPH) * 2;                            // 206,848
static const int SMEM_FINAL = (64 * APITCH + 2 * 32 * WPITCH_F + 64 * RPITCH + 64*4) * 4; // 136,192

// -------------------- device scratch ---------------------------------------
__device__ __align__(128) __half g_wlh[NLSTEPS * WSTEPH];  // [j][(s2,m)][n]
__device__ __align__(128) __half g_wrh[NRSTEPS * WSTEPH];  // step-reversed + transposed
__device__ __align__(128) float  g_wlab[10 * WSTEP];
__device__ __align__(128) float  g_left [BATCH * MDIM];
__device__ __align__(128) float  g_right[BATCH * MDIM];

// -------------------- helpers ----------------------------------------------
__device__ __forceinline__ float tf32r(float v) {
    uint32_t u; asm("cvt.rna.tf32.f32 %0, %1;" : "=r"(u) : "f"(v));
    return __uint_as_float(u);
}
__device__ __forceinline__ uint32_t smem_u32(const void* p) {
    uint32_t a;
    asm("{ .reg .u64 t; cvta.to.shared.u64 t, %1; cvt.u32.u64 %0, t; }" : "=r"(a) : "l"(p));
    return a;
}
__device__ __forceinline__ void cp16(void* d, const void* s) {
    asm volatile("cp.async.cg.shared.global [%0], [%1], 16;"
                 :: "r"(smem_u32(d)), "l"(s));
}
__device__ __forceinline__ void ldsm4(uint32_t r[4], uint32_t a) {
    asm volatile("ldmatrix.sync.aligned.m8n8.x4.shared.b16 {%0,%1,%2,%3}, [%4];"
                 : "=r"(r[0]),"=r"(r[1]),"=r"(r[2]),"=r"(r[3]) : "r"(a));
}
__device__ __forceinline__ void ldsm4t(uint32_t r[4], uint32_t a) {
    asm volatile("ldmatrix.sync.aligned.m8n8.x4.trans.shared.b16 {%0,%1,%2,%3}, [%4];"
                 : "=r"(r[0]),"=r"(r[1]),"=r"(r[2]),"=r"(r[3]) : "r"(a));
}
__device__ __forceinline__ void mma_h(float d[4], const uint32_t a[4],
                                      uint32_t b0, uint32_t b1) {
    asm volatile("mma.sync.aligned.m16n8k16.row.col.f32.f16.f16.f32 "
        "{%0,%1,%2,%3}, {%4,%5,%6,%7}, {%8,%9}, {%0,%1,%2,%3};\n"
        : "+f"(d[0]),"+f"(d[1]),"+f"(d[2]),"+f"(d[3])
        : "r"(a[0]),"r"(a[1]),"r"(a[2]),"r"(a[3]), "r"(b0),"r"(b1));
}
__device__ __forceinline__ void mma_frag(float d[4], const uint32_t a[4],
                                         uint32_t b0, uint32_t b1) {
    asm volatile("mma.sync.aligned.m16n8k8.row.col.f32.tf32.tf32.f32 "
        "{%0,%1,%2,%3}, {%4,%5,%6,%7}, {%8,%9}, {%0,%1,%2,%3};\n"
        : "+f"(d[0]),"+f"(d[1]),"+f"(d[2]),"+f"(d[3])
        : "r"(a[0]),"r"(a[1]),"r"(a[2]),"r"(a[3]), "r"(b0),"r"(b1));
}

// ======================= prep kernels ======================================
__global__ void prep_left_h(const float* __restrict__ src) {
    int i = (blockIdx.x * 256 + threadIdx.x) * 2;
    float2 v = *reinterpret_cast<const float2*>(src + i);
    *reinterpret_cast<__half2*>(g_wlh + i) = __floats2half2_rn(v.x, v.y);
}
// dst[((j*2+s2)*128+m)*128+n] = h(src[(((95-j)*2+s2)*128+n)*128+m])
__global__ void prep_right_h(const float* __restrict__ src) {
    int gid = blockIdx.x * 256 + threadIdx.x;
    int didx = gid * 2;
    int n  = didx & 127;
    int m  = (didx >> 7) & 127;
    int s2 = (didx >> 14) & 1;
    int j  = didx >> 15;
    int s  = 95 - j;
    const float* sb = src + ((size_t)(s * 2 + s2) * 128) * 128 + m;
    float v0 = __ldg(sb + (size_t)(n + 0) * 128);
    float v1 = __ldg(sb + (size_t)(n + 1) * 128);
    *reinterpret_cast<__half2*>(g_wrh + didx) = __floats2half2_rn(v0, v1);
}
__global__ void prep_label_k(const float* __restrict__ src) {
    int gid = blockIdx.x * 256 + threadIdx.x;
    int n = gid & 127, m = (gid >> 7) & 127, p = (gid >> 14) & 1, l = gid >> 15;
    g_wlab[gid] = tf32r(__ldg(src + ((p << 14) | (m << 7) | n) * 10 + l));
}

// ======================= scan kernel (fp16, v9) ============================
// 128 CTAs x 256 thr. C-tile 128x128, K=256. 8 warps: wm 0..3 (32 rows),
// wn 0..1 (64 cols). acc[2][8][4]. Full-step W double-buffered.
// Fragment double-buffering: load kc+1 frags while kc MMAs issue.
__device__ __forceinline__ void compute_step(uint32_t AsU, uint32_t WbU,
                                             float acc[2][8][4],
                                             int wm, int wn, int lane) {
    const int lrow = lane & 15, lhi = (lane >> 4) << 3;
    uint32_t a[2][2][4], b[2][4][4];
#pragma unroll
    for (int i = 0; i < 2; i++)
        ldsm4(a[0][i], AsU + (uint32_t)(((wm*32 + i*16 + lrow) * APH + lhi) * 2));
#pragma unroll
    for (int p = 0; p < 4; p++)
        ldsm4t(b[0][p], WbU + (uint32_t)((lrow * WPH + wn*64 + p*16 + lhi) * 2));
#pragma unroll
    for (int kc = 0; kc < 16; kc++) {
        const int cur = kc & 1, nxt = cur ^ 1;
        if (kc < 15) {
#pragma unroll
            for (int i = 0; i < 2; i++)
                ldsm4(a[nxt][i], AsU + (uint32_t)(((wm*32 + i*16 + lrow) * APH
                                                  + (kc+1)*16 + lhi) * 2));
#pragma unroll
            for (int p = 0; p < 4; p++)
                ldsm4t(b[nxt][p], WbU + (uint32_t)((((kc+1)*16 + lrow) * WPH
                                                   + wn*64 + p*16 + lhi) * 2));
        }
#pragma unroll
        for (int i = 0; i < 2; i++)
#pragma unroll
            for (int p = 0; p < 4; p++) {
                mma_h(acc[i][2*p],     a[cur][i], b[cur][p][0], b[cur][p][1]);
                mma_h(acc[i][2*p + 1], a[cur][i], b[cur][p][2], b[cur][p][3]);
            }
    }
}

// stage one full step: 256(k) x 128(n) fp16 (64 KB = 4096 x 16B), 16/thread
__device__ __forceinline__ void stageF(__half* dst, const __half* __restrict__ src, int tid) {
#pragma unroll
    for (int i = 0; i < 16; i++) {
        int chunk = tid + i * 256;          // 0..4095
        int row = chunk >> 4, c = (chunk & 15) * 8;
        cp16(dst + row * WPH + c, src + row * MDIM + c);
    }
    asm volatile("cp.async.commit_group;" ::: "memory");
}

__global__ __launch_bounds__(256, 1)
void scan_kernel(const float* __restrict__ x,
                 const float* __restrict__ w0,
                 const float* __restrict__ wend) {
    extern __shared__ __half smh[];
    __half* Ah = smh;                               // 128 x APH
    __half* Wb[2] = { smh + 128 * APH, smh + 128 * APH + 256 * WPH };
    const uint32_t AsU = smem_u32(Ah);
    const uint32_t WbU[2] = { smem_u32(Wb[0]), smem_u32(Wb[1]) };

    const bool is_left = blockIdx.x < 64;
    const int  b0 = (blockIdx.x & 63) * 128;
    const int  S  = is_left ? NLSTEPS : NRSTEPS;
    const __half* Wg = is_left ? g_wlh : g_wrh;
    const float* iw = is_left ? w0 : wend;
    const int tid = threadIdx.x;

    // ---- init: carry = x[iv] @ iw (fp32), A = h(xi * carry) ----
    {
        int r = tid & 127, q = tid >> 7;            // q in 0..1
        const float* xr = x + (size_t)(b0 + r) * XROW;
        int iv = is_left ? 0 : 195, xi = is_left ? 1 : 194;
        float x0 = xr[iv*2], x1 = xr[iv*2+1], xi0 = xr[xi*2], xi1 = xr[xi*2+1];
        for (int m = q * 64; m < q * 64 + 64; m++) {
            float v = x0 * iw[m] + x1 * iw[MDIM + m];
            Ah[r * APH + m]       = __float2half_rn(xi0 * v);
            Ah[r * APH + 128 + m] = __float2half_rn(xi1 * v);
        }
    }

    // prologue: stage steps 0 and 1 (one commit group each)
    stageF(Wb[0], Wg, tid);
    if (S > 1) stageF(Wb[1], Wg + WSTEPH, tid);

    const int warp = tid >> 5, lane = tid & 31, g = lane >> 2, t = lane & 3;
    const int wm = warp >> 1, wn = warp & 1;        // wm 0..3, wn 0..1
    const int pair_bar = 1 + wm;                    // named barrier per wm pair

    for (int j = 0; j < S; j++) {
        float acc[2][8][4];
#pragma unroll
        for (int i = 0; i < 2; i++)
#pragma unroll
            for (int jj = 0; jj < 8; jj++)
#pragma unroll
                for (int q = 0; q < 4; q++) acc[i][jj][q] = 0.f;

        // groups in flight: {j, j+1 (if staged)} -> wait for step j
        if (j + 1 < S) asm volatile("cp.async.wait_group 1;" ::: "memory");
        else           asm volatile("cp.async.wait_group 0;" ::: "memory");
        __syncthreads();           // W[j] + rebuilt A (+restage) visible

        // prefetch xi scalars for the epilogue (hidden under compute)
        float p00[2], p01[2], p10[2], p11[2];
        if (j + 1 < S) {
            int xin = is_left ? (2 + j) : (193 - j);
#pragma unroll
            for (int i = 0; i < 2; i++) {
                int r0 = wm * 32 + i * 16 + g;
                const float* xr0 = x + (size_t)(b0 + r0) * XROW + xin * 2;
                const float* xr1 = x + (size_t)(b0 + r0 + 8) * XROW + xin * 2;
                p00[i] = __ldg(xr0); p01[i] = __ldg(xr0 + 1);
                p10[i] = __ldg(xr1); p11[i] = __ldg(xr1 + 1);
            }
        }

        compute_step(AsU, WbU[j & 1], acc, wm, wn, lane);

        // pair barrier: both warps sharing these A rows are done reading them
        asm volatile("bar.sync %0, 64;" :: "r"(pair_bar) : "memory");

        if (j + 1 < S) {
            // epilogue: A <- h( xi(j+1) * carry_new )  (pair-private rows)
#pragma unroll
            for (int i = 0; i < 2; i++) {
                int r0 = wm * 32 + i * 16 + g;
#pragma unroll
                for (int jj = 0; jj < 8; jj++) {
                    int c0 = wn * 64 + jj * 8 + 2 * t;
                    float d0 = acc[i][jj][0], d1 = acc[i][jj][1];
                    float d2 = acc[i][jj][2], d3 = acc[i][jj][3];
                    *(__half2*)(Ah + r0 * APH + c0)             = __floats2half2_rn(p00[i]*d0, p00[i]*d1);
                    *(__half2*)(Ah + r0 * APH + 128 + c0)       = __floats2half2_rn(p01[i]*d0, p01[i]*d1);
                    *(__half2*)(Ah + (r0 + 8) * APH + c0)       = __floats2half2_rn(p10[i]*d2, p10[i]*d3);
                    *(__half2*)(Ah + (r0 + 8) * APH + 128 + c0) = __floats2half2_rn(p11[i]*d2, p11[i]*d3);
                }
            }
        } else {
            float* dst = is_left ? g_left : g_right;
#pragma unroll
            for (int i = 0; i < 2; i++) {
                int r0 = wm * 32 + i * 16 + g;
#pragma unroll
                for (int jj = 0; jj < 8; jj++) {
                    int c0 = wn * 64 + jj * 8 + 2 * t;
                    *(float2*)&dst[(size_t)(b0 + r0) * MDIM + c0]     = make_float2(acc[i][jj][0], acc[i][jj][1]);
                    *(float2*)&dst[(size_t)(b0 + r0 + 8) * MDIM + c0] = make_float2(acc[i][jj][2], acc[i][jj][3]);
                }
            }
        }

        __syncthreads();           // all compute+epilogue done: W[j&1] free,
                                   // A writes published for next step
        if (j + 2 < S)             // refill the just-freed buffer
            stageF(Wb[j & 1], Wg + (size_t)(j + 2) * WSTEPH, tid);
    }
}

// ======================= final kernel (tf32, proven) =======================
__device__ __forceinline__ void stage32f(float* dst, const float* __restrict__ src, int tid) {
#pragma unroll
    for (int i = 0; i < 4; i++) {
        int chunk = tid + i * 256, row = chunk >> 5, cc = (chunk & 31) * 4;
        cp16(dst + row * WPITCH_F + cc, src + row * MDIM + cc);
    }
    asm volatile("cp.async.commit_group;" ::: "memory");
}

__device__ __forceinline__ void compute_slice_f(const float* __restrict__ As,
                                                const float* __restrict__ Wb,
                                                int kb, float acc[2][4][4],
                                                int wm, int wn, int g, int t) {
    const uint32_t* Au = (const uint32_t*)As;
    const uint32_t* Wu = (const uint32_t*)Wb;
#pragma unroll
    for (int kk = 0; kk < 32; kk += 8) {
        uint32_t a[2][4];
#pragma unroll
        for (int i = 0; i < 2; i++) {
            int rr = wm * 32 + i * 16 + g, k = kb + kk + t;
            a[i][0] = Au[rr * APITCH + k];
            a[i][1] = Au[(rr + 8) * APITCH + k];
            a[i][2] = Au[rr * APITCH + k + 4];
            a[i][3] = Au[(rr + 8) * APITCH + k + 4];
        }
#pragma unroll
        for (int jj = 0; jj < 4; jj++) {
            int cn = wn * 32 + jj * 8 + g;
            uint32_t b0 = Wu[(kk + t) * WPITCH_F + cn];
            uint32_t b1 = Wu[(kk + t + 4) * WPITCH_F + cn];
            mma_frag(acc[0][jj], a[0], b0, b1);
            mma_frag(acc[1][jj], a[1], b0, b1);
        }
    }
}

__global__ __launch_bounds__(256, 1)
void final_kernel(const float* __restrict__ x, float* __restrict__ out) {
    extern __shared__ float smemf[];
    float* As  = smemf;
    float* Wb0 = As + 64 * APITCH;
    float* Wb1 = Wb0 + 32 * WPITCH_F;
    float* sR  = Wb1 + 32 * WPITCH_F;
    float* sP  = sR + 64 * RPITCH;

    const int b0 = blockIdx.x * 64, tid = threadIdx.x;
    {
        int rr = tid >> 2, q = tid & 3;
        const float* xr = x + (size_t)(b0 + rr) * XROW + 98 * 2;
        float xl0 = __ldg(xr), xl1 = __ldg(xr + 1);
        for (int m = q * 32; m < q * 32 + 32; m++) {
            float v = g_left[(size_t)(b0 + rr) * MDIM + m];
            As[rr * APITCH + m]       = tf32r(xl0 * v);
            As[rr * APITCH + 128 + m] = tf32r(xl1 * v);
            sR[rr * RPITCH + m] = g_right[(size_t)(b0 + rr) * MDIM + m];
        }
    }
    __syncthreads();

    const int warp = tid >> 5, lane = tid & 31, g = lane >> 2, t = lane & 3;
    const int wm = warp >> 2, wn = warp & 3;

    for (int l = 0; l < 10; l++) {
        const float* W = g_wlab + (size_t)l * WSTEP;
        float acc[2][4][4];
#pragma unroll
        for (int i = 0; i < 2; i++)
#pragma unroll
            for (int jj = 0; jj < 4; jj++)
#pragma unroll
                for (int q = 0; q < 4; q++) acc[i][jj][q] = 0.f;

        stage32f(Wb0, W, tid);
#pragma unroll 1
        for (int ks = 0; ks < 8; ks++) {
            float* cur = (ks & 1) ? Wb1 : Wb0;
            if (ks < 7) {
                stage32f((ks & 1) ? Wb0 : Wb1, W + (ks + 1) * 32 * MDIM, tid);
                asm volatile("cp.async.wait_group 1;" ::: "memory");
            } else {
                asm volatile("cp.async.wait_group 0;" ::: "memory");
            }
            __syncthreads();
            compute_slice_f(As, cur, ks * 32, acc, wm, wn, g, t);
            __syncthreads();
        }
#pragma unroll
        for (int i = 0; i < 2; i++) {
            int r0 = wm * 32 + i * 16 + g;
            float p0 = 0.f, p1 = 0.f;
#pragma unroll
            for (int jj = 0; jj < 4; jj++) {
                int c0 = wn * 32 + jj * 8 + 2 * t;
                p0 += acc[i][jj][0] * sR[r0 * RPITCH + c0]
                    + acc[i][jj][1] * sR[r0 * RPITCH + c0 + 1];
                p1 += acc[i][jj][2] * sR[(r0 + 8) * RPITCH + c0]
                    + acc[i][jj][3] * sR[(r0 + 8) * RPITCH + c0 + 1];
            }
            p0 += __shfl_xor_sync(0xffffffffu, p0, 1);
            p0 += __shfl_xor_sync(0xffffffffu, p0, 2);
            p1 += __shfl_xor_sync(0xffffffffu, p1, 1);
            p1 += __shfl_xor_sync(0xffffffffu, p1, 2);
            if (t == 0) { sP[r0 * 4 + wn] = p0; sP[(r0 + 8) * 4 + wn] = p1; }
        }
        __syncthreads();
        if (tid < 64)
            out[(size_t)(b0 + tid) * 10 + l] =
                sP[tid * 4] + sP[tid * 4 + 1] + sP[tid * 4 + 2] + sP[tid * 4 + 3];
        __syncthreads();
    }
}

// ======================= launch ============================================
extern "C" void kernel_launch(void* const* d_in, const int* in_sizes, int n_in,
                              void* d_out, int out_size) {
    const float *x = nullptr, *w0 = nullptr, *wl = nullptr,
                *wlab = nullptr, *wr = nullptr, *wend = nullptr;
    for (int i = 0; i < n_in; i++) {
        const float* p = (const float*)d_in[i];
        switch (in_sizes[i]) {
            case 3211264: x = p; break;
            case 3178496: wl = p; break;
            case 327680:  wlab = p; break;
            case 3145728: wr = p; break;
            case 256:     if (!w0) w0 = p; else wend = p; break;
            default: break;
        }
    }
    if (!x || !w0 || !wl || !wlab || !wr || !wend) return;

    cudaFuncSetAttribute(scan_kernel,  cudaFuncAttributeMaxDynamicSharedMemorySize, SMEM_SCAN);
    cudaFuncSetAttribute(final_kernel, cudaFuncAttributeMaxDynamicSharedMemorySize, SMEM_FINAL);

    prep_left_h <<<6208, 256>>>(wl);
    prep_right_h<<<6144, 256>>>(wr);
    prep_label_k<<<1280, 256>>>(wlab);
    scan_kernel <<<128, 256, SMEM_SCAN>>>(x, w0, wend);
    final_kernel<<<128, 256, SMEM_FINAL>>>(x, (float*)d_out);
}